// round 3
// baseline (speedup 1.0000x reference)
#include <cuda_runtime.h>
#include <cstdint>

#define NN 4096
#define DD 256
#define HH 8
#define DHH 32
#define EE 131072

// ---------------- scratch (device globals: allowed scratch mechanism) ----------------
__device__ float g_h[NN * DD];                      // x + pos
__device__ float g_q[HH * NN * DHH];                // [h][n][dh]
__device__ float g_k[HH * NN * DHH];
__device__ float g_v[HH * NN * DHH];
__device__ float g_att[NN * DD];                    // attention output, [n][h*32+dh]
__device__ float g_tmp[NN * DD];                    // pre-LN
__device__ float g_scores[(size_t)HH * NN * NN];    // 537 MB score tensor

// ---------------- packed fp32x2 helpers ----------------
#define PACK2(u, lo, hi) asm("mov.b64 %0, {%1,%2};" : "=l"(u) : "f"(lo), "f"(hi))
#define UNPACK2(lo, hi, u) asm("mov.b64 {%0,%1}, %2;" : "=f"(lo), "=f"(hi) : "l"(u))
#define FMA2(d, a, b) asm("fma.rn.f32x2 %0, %1, %2, %0;" : "+l"(d) : "l"(a), "l"(b))

// ---------------- 1. h = x + pos ----------------
__global__ void k_add(const float* __restrict__ x, const float* __restrict__ p) {
    int i = blockIdx.x * blockDim.x + threadIdx.x;  // over float4s
    float4 a = ((const float4*)x)[i];
    float4 b = ((const float4*)p)[i];
    ((float4*)g_h)[i] = make_float4(a.x + b.x, a.y + b.y, a.z + b.z, a.w + b.w);
}

// ---------------- 2. QKV projections (64x64 tile GEMM, head-major output) ----------------
__global__ void __launch_bounds__(256) k_qkv(
    const float* __restrict__ Wq, const float* __restrict__ bq,
    const float* __restrict__ Wk, const float* __restrict__ bk,
    const float* __restrict__ Wv, const float* __restrict__ bv) {
    const float* W;
    const float* bias;
    float* out;
    if (blockIdx.z == 0)      { W = Wq; bias = bq; out = g_q; }
    else if (blockIdx.z == 1) { W = Wk; bias = bk; out = g_k; }
    else                      { W = Wv; bias = bv; out = g_v; }

    __shared__ float As[64][33];
    __shared__ float Bs[32][65];
    const int m0 = blockIdx.y * 64, n0 = blockIdx.x * 64;
    const int tid = threadIdx.x, tx = tid & 15, ty = tid >> 4;
    float acc[4][4] = {};

    for (int kk = 0; kk < DD; kk += 32) {
        #pragma unroll
        for (int i = tid; i < 64 * 32; i += 256) {
            int r = i >> 5, c = i & 31;
            As[r][c] = g_h[(m0 + r) * DD + kk + c];
        }
        #pragma unroll
        for (int i = tid; i < 32 * 64; i += 256) {
            int r = i >> 6, c = i & 63;
            Bs[r][c] = W[(kk + r) * DD + n0 + c];
        }
        __syncthreads();
        #pragma unroll
        for (int kq = 0; kq < 32; kq++) {
            float a[4], bb[4];
            #pragma unroll
            for (int i = 0; i < 4; i++) a[i] = As[ty * 4 + i][kq];
            #pragma unroll
            for (int j = 0; j < 4; j++) bb[j] = Bs[kq][tx * 4 + j];
            #pragma unroll
            for (int i = 0; i < 4; i++)
                #pragma unroll
                for (int j = 0; j < 4; j++) acc[i][j] += a[i] * bb[j];
        }
        __syncthreads();
    }
    #pragma unroll
    for (int i = 0; i < 4; i++) {
        int row = m0 + ty * 4 + i;
        #pragma unroll
        for (int j = 0; j < 4; j++) {
            int col = n0 + tx * 4 + j;
            // [h][n][dh] layout
            out[((size_t)(col >> 5) * NN + row) * DHH + (col & 31)] = acc[i][j] + bias[col];
        }
    }
}

// ---------------- 3. scores = scale * q @ k^T  (128x128 tile, K=32, f32x2) ----------------
__global__ void __launch_bounds__(256) k_scores() {
    __shared__ __align__(16) float QsT[32][132];   // [k][row]
    __shared__ __align__(16) float KsT[32][132];
    const int hh = blockIdx.z;
    const int m0 = blockIdx.y * 128, n0 = blockIdx.x * 128;
    const float* qh = g_q + (size_t)hh * NN * DHH;
    const float* kh = g_k + (size_t)hh * NN * DHH;
    const int tid = threadIdx.x;

    #pragma unroll
    for (int i = tid; i < 128 * 32; i += 256) {
        int c = i & 31, r = i >> 5;
        QsT[c][r] = qh[(m0 + r) * DHH + c];
        KsT[c][r] = kh[(n0 + r) * DHH + c];
    }
    __syncthreads();

    const int tx = tid & 15, ty = tid >> 4;
    unsigned long long acc[8][4];
    #pragma unroll
    for (int i = 0; i < 8; i++)
        #pragma unroll
        for (int j = 0; j < 4; j++) acc[i][j] = 0ull;

    #pragma unroll 4
    for (int kq = 0; kq < 32; kq++) {
        float4 a0 = *(const float4*)&QsT[kq][ty * 8];
        float4 a1 = *(const float4*)&QsT[kq][ty * 8 + 4];
        ulonglong2 b0 = *(const ulonglong2*)&KsT[kq][tx * 8];
        ulonglong2 b1 = *(const ulonglong2*)&KsT[kq][tx * 8 + 4];
        unsigned long long bp[4] = {b0.x, b0.y, b1.x, b1.y};
        float av[8] = {a0.x, a0.y, a0.z, a0.w, a1.x, a1.y, a1.z, a1.w};
        #pragma unroll
        for (int i = 0; i < 8; i++) {
            unsigned long long ap;
            PACK2(ap, av[i], av[i]);
            #pragma unroll
            for (int j = 0; j < 4; j++) FMA2(acc[i][j], ap, bp[j]);
        }
    }

    const float scale = 0.17677669529663687f;  // 1/sqrt(32)
    float* sh = g_scores + (size_t)hh * NN * NN;
    #pragma unroll
    for (int i = 0; i < 8; i++) {
        size_t rowoff = (size_t)(m0 + ty * 8 + i) * NN + n0 + tx * 8;
        #pragma unroll
        for (int j = 0; j < 4; j++) {
            float lo, hi;
            UNPACK2(lo, hi, acc[i][j]);
            *(float2*)(sh + rowoff + 2 * j) = make_float2(lo * scale, hi * scale);
        }
    }
}

// ---------------- 4. scatter edge-type bias (atomicAdd handles duplicate edges) ----------------
// NOTE: edge_index / edge_types arrive as int32 (JAX default x64-disabled downcast).
__global__ void k_bias(const int* __restrict__ ei,
                       const int* __restrict__ et,
                       const float* __restrict__ emb) {
    int e = blockIdx.x * 256 + threadIdx.x;
    int src = ei[e];
    int dst = ei[EE + e];
    int t = et[e];
    size_t base = (size_t)src * NN + dst;
    #pragma unroll
    for (int h = 0; h < HH; h++)
        atomicAdd(g_scores + (size_t)h * NN * NN + base, emb[t * HH + h]);
}

// ---------------- 5. row softmax over 4096 cols (registers-only, 16 elems/thread) ----------------
__global__ void __launch_bounds__(256) k_softmax() {
    float* s = g_scores + (size_t)blockIdx.x * NN;
    const int tid = threadIdx.x;
    float4 v[4];
    float lmax = -3.0e38f;
    #pragma unroll
    for (int i = 0; i < 4; i++) {
        v[i] = ((float4*)s)[tid + 256 * i];
        lmax = fmaxf(lmax, fmaxf(fmaxf(v[i].x, v[i].y), fmaxf(v[i].z, v[i].w)));
    }
    #pragma unroll
    for (int o = 16; o > 0; o >>= 1) lmax = fmaxf(lmax, __shfl_xor_sync(0xffffffffu, lmax, o));
    __shared__ float smax[8], ssum[8];
    if ((tid & 31) == 0) smax[tid >> 5] = lmax;
    __syncthreads();
    float rmax = smax[0];
    #pragma unroll
    for (int i = 1; i < 8; i++) rmax = fmaxf(rmax, smax[i]);

    float lsum = 0.f;
    #pragma unroll
    for (int i = 0; i < 4; i++) {
        v[i].x = __expf(v[i].x - rmax);
        v[i].y = __expf(v[i].y - rmax);
        v[i].z = __expf(v[i].z - rmax);
        v[i].w = __expf(v[i].w - rmax);
        lsum += v[i].x + v[i].y + v[i].z + v[i].w;
    }
    #pragma unroll
    for (int o = 16; o > 0; o >>= 1) lsum += __shfl_xor_sync(0xffffffffu, lsum, o);
    if ((tid & 31) == 0) ssum[tid >> 5] = lsum;
    __syncthreads();
    float tot = 0.f;
    #pragma unroll
    for (int i = 0; i < 8; i++) tot += ssum[i];
    float inv = 1.0f / tot;
    #pragma unroll
    for (int i = 0; i < 4; i++) {
        v[i].x *= inv; v[i].y *= inv; v[i].z *= inv; v[i].w *= inv;
        ((float4*)s)[tid + 256 * i] = v[i];
    }
}

// ---------------- 6. out = attn @ v  (128 rows x 32 cols per block, f32x2) ----------------
__global__ void __launch_bounds__(256) k_av() {
    __shared__ float As[128][65];
    __shared__ __align__(16) float Vs[64][32];
    const int hh = blockIdx.z;
    const int m0 = blockIdx.x * 128;
    const float* ah = g_scores + (size_t)hh * NN * NN;
    const float* vh = g_v + (size_t)hh * NN * DHH;
    const int tid = threadIdx.x;
    const int tx = tid & 3, ty = tid >> 2;  // cols tx*8..+7, rows ty*2, ty*2+1

    unsigned long long acc[2][4];
    #pragma unroll
    for (int i = 0; i < 2; i++)
        #pragma unroll
        for (int j = 0; j < 4; j++) acc[i][j] = 0ull;

    for (int k0 = 0; k0 < NN; k0 += 64) {
        #pragma unroll
        for (int i = tid; i < 128 * 64; i += 256) {
            int r = i >> 6, c = i & 63;
            As[r][c] = ah[(size_t)(m0 + r) * NN + k0 + c];
        }
        #pragma unroll
        for (int i = tid; i < 64 * 32; i += 256) {
            int r = i >> 5, c = i & 31;
            Vs[r][c] = vh[(k0 + r) * DHH + c];
        }
        __syncthreads();
        #pragma unroll 8
        for (int kq = 0; kq < 64; kq++) {
            float a0 = As[ty * 2][kq];
            float a1 = As[ty * 2 + 1][kq];
            unsigned long long ap0, ap1;
            PACK2(ap0, a0, a0);
            PACK2(ap1, a1, a1);
            ulonglong2 b0 = *(const ulonglong2*)&Vs[kq][tx * 8];
            ulonglong2 b1 = *(const ulonglong2*)&Vs[kq][tx * 8 + 4];
            unsigned long long bp[4] = {b0.x, b0.y, b1.x, b1.y};
            #pragma unroll
            for (int j = 0; j < 4; j++) {
                FMA2(acc[0][j], ap0, bp[j]);
                FMA2(acc[1][j], ap1, bp[j]);
            }
        }
        __syncthreads();
    }
    #pragma unroll
    for (int i = 0; i < 2; i++) {
        int row = m0 + ty * 2 + i;
        #pragma unroll
        for (int j = 0; j < 4; j++) {
            float lo, hi;
            UNPACK2(lo, hi, acc[i][j]);
            *(float2*)(g_att + (size_t)row * DD + hh * DHH + tx * 8 + 2 * j) =
                make_float2(lo, hi);
        }
    }
}

// ---------------- 7. tmp = x + att @ Wo + bo ----------------
__global__ void __launch_bounds__(256) k_oproj(const float* __restrict__ Wo,
                                               const float* __restrict__ bo,
                                               const float* __restrict__ x) {
    __shared__ float As[64][33];
    __shared__ float Bs[32][65];
    const int m0 = blockIdx.y * 64, n0 = blockIdx.x * 64;
    const int tid = threadIdx.x, tx = tid & 15, ty = tid >> 4;
    float acc[4][4] = {};

    for (int kk = 0; kk < DD; kk += 32) {
        #pragma unroll
        for (int i = tid; i < 64 * 32; i += 256) {
            int r = i >> 5, c = i & 31;
            As[r][c] = g_att[(m0 + r) * DD + kk + c];
        }
        #pragma unroll
        for (int i = tid; i < 32 * 64; i += 256) {
            int r = i >> 6, c = i & 63;
            Bs[r][c] = Wo[(kk + r) * DD + n0 + c];
        }
        __syncthreads();
        #pragma unroll
        for (int kq = 0; kq < 32; kq++) {
            float a[4], bb[4];
            #pragma unroll
            for (int i = 0; i < 4; i++) a[i] = As[ty * 4 + i][kq];
            #pragma unroll
            for (int j = 0; j < 4; j++) bb[j] = Bs[kq][tx * 4 + j];
            #pragma unroll
            for (int i = 0; i < 4; i++)
                #pragma unroll
                for (int j = 0; j < 4; j++) acc[i][j] += a[i] * bb[j];
        }
        __syncthreads();
    }
    #pragma unroll
    for (int i = 0; i < 4; i++) {
        int row = m0 + ty * 4 + i;
        #pragma unroll
        for (int j = 0; j < 4; j++) {
            int col = n0 + tx * 4 + j;
            g_tmp[(size_t)row * DD + col] = acc[i][j] + bo[col] + x[(size_t)row * DD + col];
        }
    }
}

// ---------------- 8. LayerNorm (one block per row, two-pass) ----------------
__global__ void __launch_bounds__(256) k_ln(const float* __restrict__ gamma,
                                            const float* __restrict__ beta,
                                            float* __restrict__ out) {
    const int n = blockIdx.x, tid = threadIdx.x;
    float v = g_tmp[(size_t)n * DD + tid];
    __shared__ float red[8];
    float s = v;
    #pragma unroll
    for (int o = 16; o > 0; o >>= 1) s += __shfl_xor_sync(0xffffffffu, s, o);
    if ((tid & 31) == 0) red[tid >> 5] = s;
    __syncthreads();
    float tot = 0.f;
    #pragma unroll
    for (int i = 0; i < 8; i++) tot += red[i];
    float mu = tot * (1.0f / DD);
    float d = v - mu;
    __syncthreads();
    float sq = d * d;
    #pragma unroll
    for (int o = 16; o > 0; o >>= 1) sq += __shfl_xor_sync(0xffffffffu, sq, o);
    if ((tid & 31) == 0) red[tid >> 5] = sq;
    __syncthreads();
    float tot2 = 0.f;
    #pragma unroll
    for (int i = 0; i < 8; i++) tot2 += red[i];
    float var = tot2 * (1.0f / DD);
    out[(size_t)n * DD + tid] = d * rsqrtf(var + 1e-5f) * gamma[tid] + beta[tid];
}

// ---------------- launch ----------------
extern "C" void kernel_launch(void* const* d_in, const int* in_sizes, int n_in,
                              void* d_out, int out_size) {
    const float* x       = (const float*)d_in[0];
    const float* pos     = (const float*)d_in[1];
    const int* ei        = (const int*)d_in[2];
    const int* et        = (const int*)d_in[3];
    const float* Wq = (const float*)d_in[4];
    const float* bq = (const float*)d_in[5];
    const float* Wk = (const float*)d_in[6];
    const float* bk = (const float*)d_in[7];
    const float* Wv = (const float*)d_in[8];
    const float* bv = (const float*)d_in[9];
    const float* Wo = (const float*)d_in[10];
    const float* bo = (const float*)d_in[11];
    const float* emb   = (const float*)d_in[12];
    const float* gamma = (const float*)d_in[13];
    const float* beta  = (const float*)d_in[14];
    float* out = (float*)d_out;

    k_add<<<(NN * DD / 4) / 256, 256>>>(x, pos);
    k_qkv<<<dim3(DD / 64, NN / 64, 3), 256>>>(Wq, bq, Wk, bk, Wv, bv);
    k_scores<<<dim3(NN / 128, NN / 128, HH), 256>>>();
    k_bias<<<EE / 256, 256>>>(ei, et, emb);
    k_softmax<<<HH * NN, 256>>>();
    k_av<<<dim3(NN / 128, 1, HH), 256>>>();
    k_oproj<<<dim3(DD / 64, NN / 64), 256>>>(Wo, bo, x);
    k_ln<<<NN, 256>>>(gamma, beta, out);
}

// round 8
// speedup vs baseline: 1.2250x; 1.2250x over previous
#include <cuda_runtime.h>
#include <cstdint>

#define NN 4096
#define DD 256
#define HH 8
#define DHH 32
#define EE 131072
#define RT 64      // rows per flash block
#define CT 64      // column tile

// ---------------- scratch ----------------
__device__ float g_h[NN * DD];                      // x + pos
__device__ float g_q[HH * NN * DHH];                // [h][n][dh]
__device__ float g_k[HH * NN * DHH];
__device__ float g_v[HH * NN * DHH];
__device__ float g_att[NN * DD];                    // attention output [n][h*32+dh]
__device__ float g_tmp[NN * DD];                    // pre-LN
// CSR of edges keyed by source row (sorted by dst within each row)
__device__ int g_cnt[NN];
__device__ int g_cur[NN];
__device__ int g_off[NN + 1];
__device__ int g_epack[EE];                         // dst | (type<<12)

// ---------------- packed fp32x2 helpers ----------------
#define PACK2(u, lo, hi) asm("mov.b64 %0, {%1,%2};" : "=l"(u) : "f"(lo), "f"(hi))
#define UNPACK2(lo, hi, u) asm("mov.b64 {%0,%1}, %2;" : "=f"(lo), "=f"(hi) : "l"(u))
#define FMA2(d, a, b) asm("fma.rn.f32x2 %0, %1, %2, %0;" : "+l"(d) : "l"(a), "l"(b))

// ---------------- 1. h = x + pos ----------------
__global__ void k_add(const float* __restrict__ x, const float* __restrict__ p) {
    int i = blockIdx.x * blockDim.x + threadIdx.x;
    float4 a = ((const float4*)x)[i];
    float4 b = ((const float4*)p)[i];
    ((float4*)g_h)[i] = make_float4(a.x + b.x, a.y + b.y, a.z + b.z, a.w + b.w);
}

// ---------------- 2. QKV projections ----------------
__global__ void __launch_bounds__(256) k_qkv(
    const float* __restrict__ Wq, const float* __restrict__ bq,
    const float* __restrict__ Wk, const float* __restrict__ bk,
    const float* __restrict__ Wv, const float* __restrict__ bv) {
    const float* W;
    const float* bias;
    float* out;
    if (blockIdx.z == 0)      { W = Wq; bias = bq; out = g_q; }
    else if (blockIdx.z == 1) { W = Wk; bias = bk; out = g_k; }
    else                      { W = Wv; bias = bv; out = g_v; }

    __shared__ float As[64][33];
    __shared__ float Bs[32][65];
    const int m0 = blockIdx.y * 64, n0 = blockIdx.x * 64;
    const int tid = threadIdx.x, tx = tid & 15, ty = tid >> 4;
    float acc[4][4] = {};

    for (int kk = 0; kk < DD; kk += 32) {
        #pragma unroll
        for (int i = tid; i < 64 * 32; i += 256) {
            int r = i >> 5, c = i & 31;
            As[r][c] = g_h[(m0 + r) * DD + kk + c];
        }
        #pragma unroll
        for (int i = tid; i < 32 * 64; i += 256) {
            int r = i >> 6, c = i & 63;
            Bs[r][c] = W[(kk + r) * DD + n0 + c];
        }
        __syncthreads();
        #pragma unroll
        for (int kq = 0; kq < 32; kq++) {
            float a[4], bb[4];
            #pragma unroll
            for (int i = 0; i < 4; i++) a[i] = As[ty * 4 + i][kq];
            #pragma unroll
            for (int j = 0; j < 4; j++) bb[j] = Bs[kq][tx * 4 + j];
            #pragma unroll
            for (int i = 0; i < 4; i++)
                #pragma unroll
                for (int j = 0; j < 4; j++) acc[i][j] += a[i] * bb[j];
        }
        __syncthreads();
    }
    #pragma unroll
    for (int i = 0; i < 4; i++) {
        int row = m0 + ty * 4 + i;
        #pragma unroll
        for (int j = 0; j < 4; j++) {
            int col = n0 + tx * 4 + j;
            out[((size_t)(col >> 5) * NN + row) * DHH + (col & 31)] = acc[i][j] + bias[col];
        }
    }
}

// ---------------- 3. CSR build + per-row dst sort ----------------
__global__ void k_zero() {
    int i = blockIdx.x * 256 + threadIdx.x;
    if (i < NN) { g_cnt[i] = 0; g_cur[i] = 0; }
}
__global__ void k_count(const int* __restrict__ ei) {
    int e = blockIdx.x * 256 + threadIdx.x;
    atomicAdd(&g_cnt[ei[e]], 1);
}
__global__ void __launch_bounds__(1024) k_scan() {
    __shared__ int sp[1024];
    int t = threadIdx.x;
    int c0 = g_cnt[4 * t], c1 = g_cnt[4 * t + 1], c2 = g_cnt[4 * t + 2], c3 = g_cnt[4 * t + 3];
    int s = c0 + c1 + c2 + c3;
    sp[t] = s;
    __syncthreads();
    for (int off = 1; off < 1024; off <<= 1) {
        int v = (t >= off) ? sp[t - off] : 0;
        __syncthreads();
        sp[t] += v;
        __syncthreads();
    }
    int base = sp[t] - s;  // exclusive
    g_off[4 * t] = base;
    g_off[4 * t + 1] = base + c0;
    g_off[4 * t + 2] = base + c0 + c1;
    g_off[4 * t + 3] = base + c0 + c1 + c2;
    if (t == 1023) g_off[NN] = sp[t];
}
__global__ void k_scatter(const int* __restrict__ ei, const int* __restrict__ et) {
    int e = blockIdx.x * 256 + threadIdx.x;
    int src = ei[e];
    int pos = g_off[src] + atomicAdd(&g_cur[src], 1);
    g_epack[pos] = ei[EE + e] | (et[e] << 12);
}
// insertion sort each row's segment by dst (low 12 bits); one thread per row
__global__ void k_sort() {
    int r = blockIdx.x * 256 + threadIdx.x;
    if (r >= NN) return;
    int s = g_off[r], e = g_off[r + 1];
    for (int i = s + 1; i < e; i++) {
        int key = g_epack[i];
        int kd = key & 0xFFF;
        int j = i - 1;
        while (j >= s && (g_epack[j] & 0xFFF) > kd) {
            g_epack[j + 1] = g_epack[j];
            j--;
        }
        g_epack[j + 1] = key;
    }
}

// ---------------- 4. fused flash attention with sparse edge bias ----------------
// grid (NN/RT, HH), 256 threads.
__global__ void __launch_bounds__(256, 2) k_flash(const float* __restrict__ emb) {
    __shared__ float QsT[32][RT + 4];     // [dh][row]
    __shared__ float KsT[32][CT + 4];
    __shared__ float Ss[RT][CT + 4];      // score tile
    __shared__ __align__(16) float Vs[CT][32];
    __shared__ float Bs[16];

    const int h = blockIdx.y;
    const int m0 = blockIdx.x * RT;
    const int tid = threadIdx.x;
    const float* qh = g_q + (size_t)h * NN * DHH;
    const float* kh = g_k + (size_t)h * NN * DHH;
    const float* vh = g_v + (size_t)h * NN * DHH;

    if (tid < 16) Bs[tid] = emb[tid * HH + h];
    #pragma unroll
    for (int i = tid; i < RT * 32; i += 256) {
        int r = i >> 5, c = i & 31;
        QsT[c][r] = qh[(m0 + r) * DHH + c];
    }

    // QK mapping: tx cols(4), ty rows(4)
    const int tx = tid & 15, ty = tid >> 4;
    // softmax/AV mapping: rr row, q quarter
    const int rr = tid >> 2, q = tid & 3;

    // per-row edge cursor (only meaningful for q == 0 threads; sorted by dst)
    int ecur = 0, eend = 0;
    if (q == 0) {
        ecur = g_off[m0 + rr];
        eend = g_off[m0 + rr + 1];
    }

    float m_run = -3.0e38f, l_run = 0.0f;
    unsigned long long oa[4];  // 8 output dh floats, packed
    #pragma unroll
    for (int i = 0; i < 4; i++) oa[i] = 0ull;

    const float scale = 0.17677669529663687f;  // 1/sqrt(32)

    for (int j = 0; j < NN; j += CT) {
        __syncthreads();  // protect KsT/Vs/Ss reuse from previous tile
        #pragma unroll
        for (int i = tid; i < CT * 32; i += 256) {
            int r = i >> 5, c = i & 31;
            KsT[c][r] = kh[(j + r) * DHH + c];
            Vs[r][c]  = vh[(j + r) * DHH + c];
        }
        __syncthreads();

        // ---- S = scale * Q K^T (4x4 per thread, f32x2) ----
        unsigned long long acc[4][2];
        #pragma unroll
        for (int r = 0; r < 4; r++) { acc[r][0] = 0ull; acc[r][1] = 0ull; }
        #pragma unroll 4
        for (int k = 0; k < 32; k++) {
            float4 a = *(const float4*)&QsT[k][ty * 4];
            ulonglong2 b = *(const ulonglong2*)&KsT[k][tx * 4];
            float av[4] = {a.x, a.y, a.z, a.w};
            #pragma unroll
            for (int r = 0; r < 4; r++) {
                unsigned long long ap;
                PACK2(ap, av[r], av[r]);
                FMA2(acc[r][0], ap, b.x);
                FMA2(acc[r][1], ap, b.y);
            }
        }
        #pragma unroll
        for (int r = 0; r < 4; r++) {
            float s0, s1, s2, s3;
            UNPACK2(s0, s1, acc[r][0]);
            UNPACK2(s2, s3, acc[r][1]);
            *(float4*)&Ss[ty * 4 + r][tx * 4] =
                make_float4(s0 * scale, s1 * scale, s2 * scale, s3 * scale);
        }
        __syncthreads();

        // ---- sparse edge bias: sorted cursor, one thread per row (duplicate-safe) ----
        if (q == 0) {
            int lim = j + CT;
            while (ecur < eend) {
                int p = g_epack[ecur];
                int d = p & 0xFFF;
                if (d >= lim) break;
                Ss[rr][d - j] += Bs[p >> 12];
                ecur++;
            }
        }
        __syncthreads();

        // ---- online softmax over this tile (4 threads per row, 16 cols each) ----
        float vreg[16];
        float tmax = -3.0e38f;
        #pragma unroll
        for (int i = 0; i < 16; i += 4) {
            float4 t4 = *(const float4*)&Ss[rr][q * 16 + i];
            vreg[i] = t4.x; vreg[i + 1] = t4.y; vreg[i + 2] = t4.z; vreg[i + 3] = t4.w;
            tmax = fmaxf(tmax, fmaxf(fmaxf(t4.x, t4.y), fmaxf(t4.z, t4.w)));
        }
        tmax = fmaxf(tmax, __shfl_xor_sync(0xffffffffu, tmax, 1));
        tmax = fmaxf(tmax, __shfl_xor_sync(0xffffffffu, tmax, 2));
        float mnew = fmaxf(m_run, tmax);
        float corr = __expf(m_run - mnew);
        float psum = 0.0f;
        #pragma unroll
        for (int i = 0; i < 16; i++) {
            vreg[i] = __expf(vreg[i] - mnew);
            psum += vreg[i];
        }
        #pragma unroll
        for (int i = 0; i < 16; i += 4)
            *(float4*)&Ss[rr][q * 16 + i] =
                make_float4(vreg[i], vreg[i + 1], vreg[i + 2], vreg[i + 3]);
        psum += __shfl_xor_sync(0xffffffffu, psum, 1);
        psum += __shfl_xor_sync(0xffffffffu, psum, 2);
        l_run = l_run * corr + psum;
        m_run = mnew;
        // rescale output accumulator
        #pragma unroll
        for (int i = 0; i < 4; i++) {
            float lo, hi;
            UNPACK2(lo, hi, oa[i]);
            PACK2(oa[i], lo * corr, hi * corr);
        }
        __syncwarp();  // P row written by 4 same-warp threads; order before AV reads

        // ---- o += P V (1 row x 8 dh per thread) ----
        #pragma unroll 4
        for (int k = 0; k < CT; k += 4) {
            float4 p4 = *(const float4*)&Ss[rr][k];
            float pv[4] = {p4.x, p4.y, p4.z, p4.w};
            #pragma unroll
            for (int kk = 0; kk < 4; kk++) {
                ulonglong2 va = *(const ulonglong2*)&Vs[k + kk][q * 8];
                ulonglong2 vb = *(const ulonglong2*)&Vs[k + kk][q * 8 + 4];
                unsigned long long pp;
                PACK2(pp, pv[kk], pv[kk]);
                FMA2(oa[0], pp, va.x);
                FMA2(oa[1], pp, va.y);
                FMA2(oa[2], pp, vb.x);
                FMA2(oa[3], pp, vb.y);
            }
        }
    }

    // epilogue: normalize and write
    float inv = 1.0f / l_run;
    float* dst = g_att + (size_t)(m0 + rr) * DD + h * DHH + q * 8;
    #pragma unroll
    for (int i = 0; i < 4; i++) {
        float lo, hi;
        UNPACK2(lo, hi, oa[i]);
        *(float2*)(dst + 2 * i) = make_float2(lo * inv, hi * inv);
    }
}

// ---------------- 5. tmp = x + att @ Wo + bo ----------------
__global__ void __launch_bounds__(256) k_oproj(const float* __restrict__ Wo,
                                               const float* __restrict__ bo,
                                               const float* __restrict__ x) {
    __shared__ float As[64][33];
    __shared__ float Bs[32][65];
    const int m0 = blockIdx.y * 64, n0 = blockIdx.x * 64;
    const int tid = threadIdx.x, tx = tid & 15, ty = tid >> 4;
    float acc[4][4] = {};

    for (int kk = 0; kk < DD; kk += 32) {
        #pragma unroll
        for (int i = tid; i < 64 * 32; i += 256) {
            int r = i >> 5, c = i & 31;
            As[r][c] = g_att[(m0 + r) * DD + kk + c];
        }
        #pragma unroll
        for (int i = tid; i < 32 * 64; i += 256) {
            int r = i >> 6, c = i & 63;
            Bs[r][c] = Wo[(kk + r) * DD + n0 + c];
        }
        __syncthreads();
        #pragma unroll
        for (int kq = 0; kq < 32; kq++) {
            float a[4], bb[4];
            #pragma unroll
            for (int i = 0; i < 4; i++) a[i] = As[ty * 4 + i][kq];
            #pragma unroll
            for (int j = 0; j < 4; j++) bb[j] = Bs[kq][tx * 4 + j];
            #pragma unroll
            for (int i = 0; i < 4; i++)
                #pragma unroll
                for (int j = 0; j < 4; j++) acc[i][j] += a[i] * bb[j];
        }
        __syncthreads();
    }
    #pragma unroll
    for (int i = 0; i < 4; i++) {
        int row = m0 + ty * 4 + i;
        #pragma unroll
        for (int j = 0; j < 4; j++) {
            int col = n0 + tx * 4 + j;
            g_tmp[(size_t)row * DD + col] = acc[i][j] + bo[col] + x[(size_t)row * DD + col];
        }
    }
}

// ---------------- 6. LayerNorm ----------------
__global__ void __launch_bounds__(256) k_ln(const float* __restrict__ gamma,
                                            const float* __restrict__ beta,
                                            float* __restrict__ out) {
    const int n = blockIdx.x, tid = threadIdx.x;
    float v = g_tmp[(size_t)n * DD + tid];
    __shared__ float red[8];
    float s = v;
    #pragma unroll
    for (int o = 16; o > 0; o >>= 1) s += __shfl_xor_sync(0xffffffffu, s, o);
    if ((tid & 31) == 0) red[tid >> 5] = s;
    __syncthreads();
    float tot = 0.f;
    #pragma unroll
    for (int i = 0; i < 8; i++) tot += red[i];
    float mu = tot * (1.0f / DD);
    float d = v - mu;
    __syncthreads();
    float sq = d * d;
    #pragma unroll
    for (int o = 16; o > 0; o >>= 1) sq += __shfl_xor_sync(0xffffffffu, sq, o);
    if ((tid & 31) == 0) red[tid >> 5] = sq;
    __syncthreads();
    float tot2 = 0.f;
    #pragma unroll
    for (int i = 0; i < 8; i++) tot2 += red[i];
    float var = tot2 * (1.0f / DD);
    out[(size_t)n * DD + tid] = d * rsqrtf(var + 1e-5f) * gamma[tid] + beta[tid];
}

// ---------------- launch ----------------
extern "C" void kernel_launch(void* const* d_in, const int* in_sizes, int n_in,
                              void* d_out, int out_size) {
    const float* x       = (const float*)d_in[0];
    const float* pos     = (const float*)d_in[1];
    const int* ei        = (const int*)d_in[2];
    const int* et        = (const int*)d_in[3];
    const float* Wq = (const float*)d_in[4];
    const float* bq = (const float*)d_in[5];
    const float* Wk = (const float*)d_in[6];
    const float* bk = (const float*)d_in[7];
    const float* Wv = (const float*)d_in[8];
    const float* bv = (const float*)d_in[9];
    const float* Wo = (const float*)d_in[10];
    const float* bo = (const float*)d_in[11];
    const float* emb   = (const float*)d_in[12];
    const float* gamma = (const float*)d_in[13];
    const float* beta  = (const float*)d_in[14];
    float* out = (float*)d_out;

    k_add<<<(NN * DD / 4) / 256, 256>>>(x, pos);
    k_qkv<<<dim3(DD / 64, NN / 64, 3), 256>>>(Wq, bq, Wk, bk, Wv, bv);
    k_zero<<<(NN + 255) / 256, 256>>>();
    k_count<<<EE / 256, 256>>>(ei);
    k_scan<<<1, 1024>>>();
    k_scatter<<<EE / 256, 256>>>(ei, et);
    k_sort<<<(NN + 255) / 256, 256>>>();
    k_flash<<<dim3(NN / RT, HH), 256>>>(emb);
    k_oproj<<<dim3(DD / 64, NN / 64), 256>>>(Wo, bo, x);
    k_ln<<<NN, 256>>>(gamma, beta, out);
}

// round 10
// speedup vs baseline: 2.7068x; 2.2096x over previous
#include <cuda_runtime.h>
#include <cuda_bf16.h>
#include <cstdint>

#define NN 4096
#define DD 256
#define HH 8
#define DHH 32
#define EE 131072

// ---------------- scratch ----------------
__device__ float g_h[NN * DD];
__device__ float g_q[HH * NN * DHH];
__device__ float g_k[HH * NN * DHH];
__device__ float g_v[HH * NN * DHH];
__device__ float g_att[NN * DD];      // unnormalized attn out, then normalized in place
__device__ float g_l[HH * NN];        // row sums
__device__ float g_tmp[NN * DD];
// CSR of edges keyed by source row (sorted by dst within row)
__device__ int g_cnt[NN];
__device__ int g_cur[NN];
__device__ int g_off[NN + 1];
__device__ int g_epack[EE];           // dst | (type<<12)
// split-bf16 operands
__device__ __nv_bfloat16 g_qs[HH * NN * 64];   // per row: [hi 32][lo 32], q pre-scaled
__device__ __nv_bfloat16 g_ks[HH * NN * 64];
__device__ __nv_bfloat16 g_vth[HH * 32 * NN];  // V^T hi  [h][d][n]
__device__ __nv_bfloat16 g_vtl[HH * 32 * NN];  // V^T lo

// ---------------- smem layout for k_flash3 (dynamic) ----------------
#define OQ   0
#define OKK  18432
#define OVH  36864
#define OVL  45568
#define SM3  54272      // Q/K: 128 rows * 144B ; Vt: 32 rows * 272B (x2)

__device__ __forceinline__ uint32_t s2u(const void* p) {
    uint32_t a;
    asm("{ .reg .u64 t; cvta.to.shared.u64 t, %1; cvt.u32.u64 %0, t; }" : "=r"(a) : "l"(p));
    return a;
}

// fast exp on the FMA pipe: e^s = 2^(s*log2e), round via magic constant, deg-5 poly
__device__ __forceinline__ float fexp(float s) {
    float t = s * 1.4426950408889634f;
    float z = t + 12582912.0f;                     // 1.5*2^23: RN-to-int in mantissa
    int ii = __float_as_int(z);                    // low bits = round(t) (bias cancels <<23)
    float r = t - (z - 12582912.0f);
    float p = 1.8775767e-3f;
    p = fmaf(p, r, 8.9893397e-3f);
    p = fmaf(p, r, 5.5826318e-2f);
    p = fmaf(p, r, 2.4015361e-1f);
    p = fmaf(p, r, 6.9315308e-1f);
    p = fmaf(p, r, 1.0f);
    return __int_as_float(__float_as_int(p) + (ii << 23));
}

#define LDM_X2(r_, a_)                                                         \
    asm volatile("ldmatrix.sync.aligned.m8n8.x2.shared.b16 {%0,%1}, [%2];"     \
                 : "=r"((r_)[0]), "=r"((r_)[1]) : "r"(a_))
#define LDM_X4(r_, a_)                                                         \
    asm volatile("ldmatrix.sync.aligned.m8n8.x4.shared.b16 {%0,%1,%2,%3}, [%4];" \
                 : "=r"((r_)[0]), "=r"((r_)[1]), "=r"((r_)[2]), "=r"((r_)[3]) : "r"(a_))
#define MMA_BF16(c_, a_, b_)                                                   \
    asm volatile("mma.sync.aligned.m16n8k16.row.col.f32.bf16.bf16.f32 "        \
                 "{%0,%1,%2,%3}, {%4,%5,%6,%7}, {%8,%9}, {%0,%1,%2,%3};"       \
                 : "+f"((c_)[0]), "+f"((c_)[1]), "+f"((c_)[2]), "+f"((c_)[3])  \
                 : "r"((a_)[0]), "r"((a_)[1]), "r"((a_)[2]), "r"((a_)[3]),     \
                   "r"((b_)[0]), "r"((b_)[1]))

// ---------------- 1. h = x + pos ----------------
__global__ void k_add(const float* __restrict__ x, const float* __restrict__ p) {
    int i = blockIdx.x * blockDim.x + threadIdx.x;
    float4 a = ((const float4*)x)[i];
    float4 b = ((const float4*)p)[i];
    ((float4*)g_h)[i] = make_float4(a.x + b.x, a.y + b.y, a.z + b.z, a.w + b.w);
}

// ---------------- 2. QKV projections ----------------
__global__ void __launch_bounds__(256) k_qkv(
    const float* __restrict__ Wq, const float* __restrict__ bq,
    const float* __restrict__ Wk, const float* __restrict__ bk,
    const float* __restrict__ Wv, const float* __restrict__ bv) {
    const float* W;
    const float* bias;
    float* out;
    if (blockIdx.z == 0)      { W = Wq; bias = bq; out = g_q; }
    else if (blockIdx.z == 1) { W = Wk; bias = bk; out = g_k; }
    else                      { W = Wv; bias = bv; out = g_v; }

    __shared__ float As[64][33];
    __shared__ float Bs2[32][65];
    const int m0 = blockIdx.y * 64, n0 = blockIdx.x * 64;
    const int tid = threadIdx.x, tx = tid & 15, ty = tid >> 4;
    float acc[4][4] = {};

    for (int kk = 0; kk < DD; kk += 32) {
        #pragma unroll
        for (int i = tid; i < 64 * 32; i += 256) {
            int r = i >> 5, c = i & 31;
            As[r][c] = g_h[(m0 + r) * DD + kk + c];
        }
        #pragma unroll
        for (int i = tid; i < 32 * 64; i += 256) {
            int r = i >> 6, c = i & 63;
            Bs2[r][c] = W[(kk + r) * DD + n0 + c];
        }
        __syncthreads();
        #pragma unroll
        for (int kq = 0; kq < 32; kq++) {
            float a[4], bb[4];
            #pragma unroll
            for (int i = 0; i < 4; i++) a[i] = As[ty * 4 + i][kq];
            #pragma unroll
            for (int j = 0; j < 4; j++) bb[j] = Bs2[kq][tx * 4 + j];
            #pragma unroll
            for (int i = 0; i < 4; i++)
                #pragma unroll
                for (int j = 0; j < 4; j++) acc[i][j] += a[i] * bb[j];
        }
        __syncthreads();
    }
    #pragma unroll
    for (int i = 0; i < 4; i++) {
        int row = m0 + ty * 4 + i;
        #pragma unroll
        for (int j = 0; j < 4; j++) {
            int col = n0 + tx * 4 + j;
            out[((size_t)(col >> 5) * NN + row) * DHH + (col & 31)] = acc[i][j] + bias[col];
        }
    }
}

// ---------------- 3. split to bf16 hi/lo ----------------
__global__ void k_split_qk() {
    int idx = blockIdx.x * 256 + threadIdx.x;
    int which = idx >> 15;                        // 0=q (scaled), 1=k
    int r = idx & 32767;                          // h*NN+n
    const float* src = (which ? g_k : g_q) + (size_t)r * 32;
    __nv_bfloat16* dst = (which ? g_ks : g_qs) + (size_t)r * 64;
    float sc = which ? 1.0f : 0.17677669529663687f;
    #pragma unroll
    for (int i = 0; i < 32; i++) {
        float v = src[i] * sc;
        __nv_bfloat16 hi = __float2bfloat16(v);
        dst[i] = hi;
        dst[32 + i] = __float2bfloat16(v - __bfloat162float(hi));
    }
}
__global__ void k_split_vt() {
    int idx = blockIdx.x * 256 + threadIdx.x;     // h*NN+n
    int hh2 = idx >> 12, n = idx & 4095;
    const float* src = g_v + (size_t)idx * 32;
    #pragma unroll
    for (int d = 0; d < 32; d++) {
        float v = src[d];
        __nv_bfloat16 hi = __float2bfloat16(v);
        size_t o = (size_t)(hh2 * 32 + d) * NN + n;
        g_vth[o] = hi;
        g_vtl[o] = __float2bfloat16(v - __bfloat162float(hi));
    }
}

// ---------------- 4. CSR build + per-row dst sort ----------------
__global__ void k_zero() {
    int i = blockIdx.x * 256 + threadIdx.x;
    if (i < NN) { g_cnt[i] = 0; g_cur[i] = 0; }
}
__global__ void k_count(const int* __restrict__ ei) {
    int e = blockIdx.x * 256 + threadIdx.x;
    atomicAdd(&g_cnt[ei[e]], 1);
}
__global__ void __launch_bounds__(1024) k_scan() {
    __shared__ int sp[1024];
    int t = threadIdx.x;
    int c0 = g_cnt[4 * t], c1 = g_cnt[4 * t + 1], c2 = g_cnt[4 * t + 2], c3 = g_cnt[4 * t + 3];
    int s = c0 + c1 + c2 + c3;
    sp[t] = s;
    __syncthreads();
    for (int off = 1; off < 1024; off <<= 1) {
        int v = (t >= off) ? sp[t - off] : 0;
        __syncthreads();
        sp[t] += v;
        __syncthreads();
    }
    int base = sp[t] - s;
    g_off[4 * t] = base;
    g_off[4 * t + 1] = base + c0;
    g_off[4 * t + 2] = base + c0 + c1;
    g_off[4 * t + 3] = base + c0 + c1 + c2;
    if (t == 1023) g_off[NN] = sp[t];
}
__global__ void k_scatter(const int* __restrict__ ei, const int* __restrict__ et) {
    int e = blockIdx.x * 256 + threadIdx.x;
    int src = ei[e];
    int pos = g_off[src] + atomicAdd(&g_cur[src], 1);
    g_epack[pos] = ei[EE + e] | (et[e] << 12);
}
__global__ void k_sort() {
    int r = blockIdx.x * 256 + threadIdx.x;
    if (r >= NN) return;
    int s = g_off[r], e = g_off[r + 1];
    for (int i = s + 1; i < e; i++) {
        int key = g_epack[i];
        int kd = key & 0xFFF;
        int j = i - 1;
        while (j >= s && (g_epack[j] & 0xFFF) > kd) {
            g_epack[j + 1] = g_epack[j];
            j--;
        }
        g_epack[j + 1] = key;
    }
}

// ---------------- 5. dense attention via mma.sync (no bias), unnormalized ----------------
// grid (NN/128, HH), 256 threads (8 warps x 16 rows). O and l written unnormalized.
__global__ void __launch_bounds__(256, 2) k_flash3() {
    extern __shared__ char sm[];
    const uint32_t sb = s2u(sm);
    const int tid = threadIdx.x, w = tid >> 5, lane = tid & 31;
    const int h = blockIdx.y, m0 = blockIdx.x * 128;
    const int g = lane >> 2, c = lane & 3;

    // stage Q tile [128 rows x 128B (hi|lo)] with 144B row pitch
    {
        const uint4* qsrc = ((const uint4*)g_qs) + (size_t)(h * NN + m0) * 8;
        for (int t2 = tid; t2 < 1024; t2 += 256) {
            int r = t2 >> 3, u = t2 & 7;
            *(uint4*)(sm + OQ + r * 144 + u * 16) = qsrc[r * 8 + u];
        }
    }
    __syncthreads();

    // persistent Q A-fragments: [Qh u0][Qh u1][Ql u0][Ql u1]
    uint32_t qf[4][4];
    {
        int r = (lane & 7) + ((lane >> 3) & 1) * 8;
        uint32_t base = sb + OQ + (w * 16 + r) * 144 + (lane >> 4) * 16;
        #pragma unroll
        for (int s = 0; s < 4; s++) LDM_X4(qf[s], base + s * 32);
    }

    float oacc[4][4];
    #pragma unroll
    for (int d = 0; d < 4; d++)
        #pragma unroll
        for (int i = 0; i < 4; i++) oacc[d][i] = 0.0f;
    float l0 = 0.0f, l1 = 0.0f;

    // per-lane ldmatrix base addresses (lanes 0-15 meaningful for .x2)
    const uint32_t kbase = sb + OKK + (lane & 7) * 144 + ((lane >> 3) & 1) * 16;
    const uint32_t vbh = sb + OVH + (lane & 7) * 272 + ((lane >> 3) & 1) * 16;
    const uint32_t vbl = sb + OVL + (lane & 7) * 272 + ((lane >> 3) & 1) * 16;

    for (int j = 0; j < NN; j += 128) {
        __syncthreads();
        // K tile
        {
            const uint4* ksrc = ((const uint4*)g_ks) + (size_t)(h * NN + j) * 8;
            for (int t2 = tid; t2 < 1024; t2 += 256) {
                int r = t2 >> 3, u = t2 & 7;
                *(uint4*)(sm + OKK + r * 144 + u * 16) = ksrc[r * 8 + u];
            }
        }
        // V^T tiles (hi, lo): 32 dh-rows x 256B with 272B pitch
        {
            for (int t2 = tid; t2 < 512; t2 += 256) {
                int d = t2 >> 4, u = t2 & 15;
                size_t gi = ((size_t)(h * 32 + d) * NN + j) / 8 + u;
                *(uint4*)(sm + OVH + d * 272 + u * 16) = ((const uint4*)g_vth)[gi];
                *(uint4*)(sm + OVL + d * 272 + u * 16) = ((const uint4*)g_vtl)[gi];
            }
        }
        __syncthreads();

        #pragma unroll 1
        for (int kg = 0; kg < 8; kg++) {
            // ---- S for column tiles nt0=2kg, nt1=2kg+1 (16 cols total) ----
            float sa[4] = {0.f, 0.f, 0.f, 0.f};
            float sbv[4] = {0.f, 0.f, 0.f, 0.f};
            uint32_t b0[2], b1[2];
            uint32_t ka0 = kbase + (2 * kg) * (8 * 144);
            uint32_t ka1 = kbase + (2 * kg + 1) * (8 * 144);
            // Kh u0 / u1 for nt0
            LDM_X2(b0, ka0);        LDM_X2(b1, ka0 + 32);
            MMA_BF16(sa, qf[0], b0); MMA_BF16(sa, qf[1], b1);
            MMA_BF16(sa, qf[2], b0); MMA_BF16(sa, qf[3], b1);
            // Kl u0/u1 for nt0
            LDM_X2(b0, ka0 + 64);   LDM_X2(b1, ka0 + 96);
            MMA_BF16(sa, qf[0], b0); MMA_BF16(sa, qf[1], b1);
            // nt1
            LDM_X2(b0, ka1);        LDM_X2(b1, ka1 + 32);
            MMA_BF16(sbv, qf[0], b0); MMA_BF16(sbv, qf[1], b1);
            MMA_BF16(sbv, qf[2], b0); MMA_BF16(sbv, qf[3], b1);
            LDM_X2(b0, ka1 + 64);   LDM_X2(b1, ka1 + 96);
            MMA_BF16(sbv, qf[0], b0); MMA_BF16(sbv, qf[1], b1);

            // ---- exp (poly, fma pipe) + row-sum + pack to bf16 hi/lo A-frags ----
            #pragma unroll
            for (int i = 0; i < 4; i++) { sa[i] = fexp(sa[i]); sbv[i] = fexp(sbv[i]); }
            l0 += sa[0] + sa[1] + sbv[0] + sbv[1];
            l1 += sa[2] + sa[3] + sbv[2] + sbv[3];

            uint32_t ah[4], al[4];
            // reg k-pair layout: low half = even col (c0), high half = odd col (c1)
            asm("cvt.rn.bf16x2.f32 %0, %1, %2;" : "=r"(ah[0]) : "f"(sa[1]), "f"(sa[0]));
            asm("cvt.rn.bf16x2.f32 %0, %1, %2;" : "=r"(ah[1]) : "f"(sa[3]), "f"(sa[2]));
            asm("cvt.rn.bf16x2.f32 %0, %1, %2;" : "=r"(ah[2]) : "f"(sbv[1]), "f"(sbv[0]));
            asm("cvt.rn.bf16x2.f32 %0, %1, %2;" : "=r"(ah[3]) : "f"(sbv[3]), "f"(sbv[2]));
            #pragma unroll
            for (int i = 0; i < 2; i++) {
                float e0 = (i ? sbv[0] : sa[0]), e1 = (i ? sbv[1] : sa[1]);
                float e2 = (i ? sbv[2] : sa[2]), e3 = (i ? sbv[3] : sa[3]);
                uint32_t h01 = ah[i * 2], h23 = ah[i * 2 + 1];
                float r0 = __uint_as_float(h01 << 16);
                float r1 = __uint_as_float(h01 & 0xFFFF0000u);
                float r2 = __uint_as_float(h23 << 16);
                float r3 = __uint_as_float(h23 & 0xFFFF0000u);
                asm("cvt.rn.bf16x2.f32 %0, %1, %2;" : "=r"(al[i * 2]) : "f"(e1 - r1), "f"(e0 - r0));
                asm("cvt.rn.bf16x2.f32 %0, %1, %2;" : "=r"(al[i * 2 + 1]) : "f"(e3 - r3), "f"(e2 - r2));
            }

            // ---- O += Ph*Vh + Ph*Vl + Pl*Vh for this k16 group ----
            #pragma unroll
            for (int d = 0; d < 4; d++) {
                uint32_t vh[2], vl[2];
                LDM_X2(vh, vbh + d * (8 * 272) + kg * 32);
                LDM_X2(vl, vbl + d * (8 * 272) + kg * 32);
                MMA_BF16(oacc[d], ah, vh);
                MMA_BF16(oacc[d], ah, vl);
                MMA_BF16(oacc[d], al, vh);
            }
        }
    }

    // epilogue: reduce row sums over the 4 lanes sharing a row, store l and O
    l0 += __shfl_xor_sync(0xffffffffu, l0, 1);
    l0 += __shfl_xor_sync(0xffffffffu, l0, 2);
    l1 += __shfl_xor_sync(0xffffffffu, l1, 1);
    l1 += __shfl_xor_sync(0xffffffffu, l1, 2);
    int row0 = m0 + w * 16 + g;
    if (c == 0) {
        g_l[h * NN + row0] = l0;
        g_l[h * NN + row0 + 8] = l1;
    }
    float* o0 = g_att + (size_t)row0 * DD + h * 32;
    float* o1 = g_att + (size_t)(row0 + 8) * DD + h * 32;
    #pragma unroll
    for (int d = 0; d < 4; d++) {
        *(float2*)(o0 + d * 8 + 2 * c) = make_float2(oacc[d][0], oacc[d][1]);
        *(float2*)(o1 + d * 8 + 2 * c) = make_float2(oacc[d][2], oacc[d][3]);
    }
}

// ---------------- 6. sparse edge-bias correction ----------------
// one thread per (row, h); edges sorted by dst; duplicate dst coalesced (sum biases).
__global__ void __launch_bounds__(256) k_corr(const float* __restrict__ emb) {
    int t = blockIdx.x * 256 + threadIdx.x;     // 32768
    int row = t >> 3, h = t & 7;
    int e = g_off[row], end = g_off[row + 1];
    if (e >= end) return;

    const float* qp = g_q + ((size_t)h * NN + row) * 32;
    float4 qv[8];
    #pragma unroll
    for (int i = 0; i < 8; i++) qv[i] = ((const float4*)qp)[i];
    const float* kh_ = g_k + (size_t)h * NN * 32;
    const float* vh_ = g_v + (size_t)h * NN * 32;

    float4 oa[8];
    #pragma unroll
    for (int i = 0; i < 8; i++) oa[i] = make_float4(0.f, 0.f, 0.f, 0.f);
    float lacc = 0.0f;
    const float scale = 0.17677669529663687f;

    while (e < end) {
        int pk = g_epack[e];
        int d = pk & 0xFFF;
        float bs = emb[(pk >> 12) * HH + h];
        e++;
        while (e < end && (g_epack[e] & 0xFFF) == d) {
            bs += emb[(g_epack[e] >> 12) * HH + h];
            e++;
        }
        const float4* kp = (const float4*)(kh_ + (size_t)d * 32);
        float s = 0.0f;
        #pragma unroll
        for (int i = 0; i < 8; i++) {
            float4 kk = kp[i];
            s += qv[i].x * kk.x + qv[i].y * kk.y + qv[i].z * kk.z + qv[i].w * kk.w;
        }
        float wgt = __expf(s * scale) * (__expf(bs) - 1.0f);
        lacc += wgt;
        const float4* vp = (const float4*)(vh_ + (size_t)d * 32);
        #pragma unroll
        for (int i = 0; i < 8; i++) {
            float4 vv = vp[i];
            oa[i].x += wgt * vv.x; oa[i].y += wgt * vv.y;
            oa[i].z += wgt * vv.z; oa[i].w += wgt * vv.w;
        }
    }

    g_l[h * NN + row] += lacc;
    float* dst = g_att + (size_t)row * DD + h * 32;
    #pragma unroll
    for (int i = 0; i < 8; i++) {
        float4 cur = ((float4*)dst)[i];
        ((float4*)dst)[i] = make_float4(cur.x + oa[i].x, cur.y + oa[i].y,
                                        cur.z + oa[i].z, cur.w + oa[i].w);
    }
}

// ---------------- 7. normalize O by row sums ----------------
__global__ void k_norm() {
    int i = blockIdx.x * 256 + threadIdx.x;     // float4 index over N*D
    int n = i >> 6, c4 = i & 63;
    int hh2 = c4 >> 3;
    float inv = 1.0f / g_l[hh2 * NN + n];
    float4 v = ((float4*)g_att)[i];
    ((float4*)g_att)[i] = make_float4(v.x * inv, v.y * inv, v.z * inv, v.w * inv);
}

// ---------------- 8. tmp = x + att @ Wo + bo ----------------
__global__ void __launch_bounds__(256) k_oproj(const float* __restrict__ Wo,
                                               const float* __restrict__ bo,
                                               const float* __restrict__ x) {
    __shared__ float As[64][33];
    __shared__ float Bs2[32][65];
    const int m0 = blockIdx.y * 64, n0 = blockIdx.x * 64;
    const int tid = threadIdx.x, tx = tid & 15, ty = tid >> 4;
    float acc[4][4] = {};

    for (int kk = 0; kk < DD; kk += 32) {
        #pragma unroll
        for (int i = tid; i < 64 * 32; i += 256) {
            int r = i >> 5, c = i & 31;
            As[r][c] = g_att[(m0 + r) * DD + kk + c];
        }
        #pragma unroll
        for (int i = tid; i < 32 * 64; i += 256) {
            int r = i >> 6, c = i & 63;
            Bs2[r][c] = Wo[(kk + r) * DD + n0 + c];
        }
        __syncthreads();
        #pragma unroll
        for (int kq = 0; kq < 32; kq++) {
            float a[4], bb[4];
            #pragma unroll
            for (int i = 0; i < 4; i++) a[i] = As[ty * 4 + i][kq];
            #pragma unroll
            for (int j = 0; j < 4; j++) bb[j] = Bs2[kq][tx * 4 + j];
            #pragma unroll
            for (int i = 0; i < 4; i++)
                #pragma unroll
                for (int j = 0; j < 4; j++) acc[i][j] += a[i] * bb[j];
        }
        __syncthreads();
    }
    #pragma unroll
    for (int i = 0; i < 4; i++) {
        int row = m0 + ty * 4 + i;
        #pragma unroll
        for (int j = 0; j < 4; j++) {
            int col = n0 + tx * 4 + j;
            g_tmp[(size_t)row * DD + col] = acc[i][j] + bo[col] + x[(size_t)row * DD + col];
        }
    }
}

// ---------------- 9. LayerNorm ----------------
__global__ void __launch_bounds__(256) k_ln(const float* __restrict__ gamma,
                                            const float* __restrict__ beta,
                                            float* __restrict__ out) {
    const int n = blockIdx.x, tid = threadIdx.x;
    float v = g_tmp[(size_t)n * DD + tid];
    __shared__ float red[8];
    float s = v;
    #pragma unroll
    for (int o = 16; o > 0; o >>= 1) s += __shfl_xor_sync(0xffffffffu, s, o);
    if ((tid & 31) == 0) red[tid >> 5] = s;
    __syncthreads();
    float tot = 0.f;
    #pragma unroll
    for (int i = 0; i < 8; i++) tot += red[i];
    float mu = tot * (1.0f / DD);
    float d = v - mu;
    __syncthreads();
    float sq = d * d;
    #pragma unroll
    for (int o = 16; o > 0; o >>= 1) sq += __shfl_xor_sync(0xffffffffu, sq, o);
    if ((tid & 31) == 0) red[tid >> 5] = sq;
    __syncthreads();
    float tot2 = 0.f;
    #pragma unroll
    for (int i = 0; i < 8; i++) tot2 += red[i];
    float var = tot2 * (1.0f / DD);
    out[(size_t)n * DD + tid] = d * rsqrtf(var + 1e-5f) * gamma[tid] + beta[tid];
}

// ---------------- launch ----------------
extern "C" void kernel_launch(void* const* d_in, const int* in_sizes, int n_in,
                              void* d_out, int out_size) {
    const float* x       = (const float*)d_in[0];
    const float* pos     = (const float*)d_in[1];
    const int* ei        = (const int*)d_in[2];
    const int* et        = (const int*)d_in[3];
    const float* Wq = (const float*)d_in[4];
    const float* bq = (const float*)d_in[5];
    const float* Wk = (const float*)d_in[6];
    const float* bk = (const float*)d_in[7];
    const float* Wv = (const float*)d_in[8];
    const float* bv = (const float*)d_in[9];
    const float* Wo = (const float*)d_in[10];
    const float* bo = (const float*)d_in[11];
    const float* emb   = (const float*)d_in[12];
    const float* gamma = (const float*)d_in[13];
    const float* beta  = (const float*)d_in[14];
    float* out = (float*)d_out;

    cudaFuncSetAttribute(k_flash3, cudaFuncAttributeMaxDynamicSharedMemorySize, SM3);

    k_add<<<(NN * DD / 4) / 256, 256>>>(x, pos);
    k_qkv<<<dim3(DD / 64, NN / 64, 3), 256>>>(Wq, bq, Wk, bk, Wv, bv);
    k_split_qk<<<2 * HH * NN / 256, 256>>>();
    k_split_vt<<<HH * NN / 256, 256>>>();
    k_zero<<<(NN + 255) / 256, 256>>>();
    k_count<<<EE / 256, 256>>>(ei);
    k_scan<<<1, 1024>>>();
    k_scatter<<<EE / 256, 256>>>(ei, et);
    k_sort<<<(NN + 255) / 256, 256>>>();
    k_flash3<<<dim3(NN / 128, HH), 256, SM3>>>();
    k_corr<<<(NN * HH) / 256, 256>>>(emb);
    k_norm<<<(NN * DD / 4) / 256, 256>>>();
    k_oproj<<<dim3(DD / 64, NN / 64), 256>>>(Wo, bo, x);
    k_ln<<<NN, 256>>>(gamma, beta, out);
}

// round 11
// speedup vs baseline: 3.3843x; 1.2503x over previous
#include <cuda_runtime.h>
#include <cuda_bf16.h>
#include <cstdint>

#define NN 4096
#define DD 256
#define HH 8
#define DHH 32
#define EE 131072

// ---------------- scratch ----------------
__device__ float g_q[HH * NN * DHH];
__device__ float g_k[HH * NN * DHH];
__device__ float g_v[HH * NN * DHH];
__device__ float g_att[NN * DD];      // unnormalized attn out
__device__ float g_l[HH * NN];        // row sums
__device__ float g_tmp[NN * DD];
// CSR of edges keyed by source row (sorted by dst within row)
__device__ int g_cnt[NN];
__device__ int g_cur[NN];
__device__ int g_off[NN + 1];
__device__ int g_epack[EE];           // dst | (type<<12)
// split-bf16 operands
__device__ __nv_bfloat16 g_qs[HH * NN * 64];   // per row: [hi 32][lo 32], q pre-scaled
__device__ __nv_bfloat16 g_ks[HH * NN * 64];
__device__ __nv_bfloat16 g_vth[HH * 32 * NN];  // V^T hi  [h][d][n]
__device__ __nv_bfloat16 g_vtl[HH * 32 * NN];  // V^T lo

// ---------------- flash3 smem layout (dynamic, double-buffered K/V) ----------------
#define OQ    0
#define OKB   18432                 // K bufs: +bi*18432  (128 x 144B)
#define OVB   55296                 // V bufs: +bi*17408; hi at +0, lo at +8704 (32 x 272B)
#define SM3   90112

// ---------------- packed fp32x2 helpers ----------------
#define PACK2(u, lo, hi) asm("mov.b64 %0, {%1,%2};" : "=l"(u) : "f"(lo), "f"(hi))
#define UNPACK2(lo, hi, u) asm("mov.b64 {%0,%1}, %2;" : "=f"(lo), "=f"(hi) : "l"(u))
#define FMA2(d, a, b) asm("fma.rn.f32x2 %0, %1, %2, %0;" : "+l"(d) : "l"(a), "l"(b))

__device__ __forceinline__ uint32_t s2u(const void* p) {
    uint32_t a;
    asm("{ .reg .u64 t; cvta.to.shared.u64 t, %1; cvt.u32.u64 %0, t; }" : "=r"(a) : "l"(p));
    return a;
}

// fast exp on the FMA pipe
__device__ __forceinline__ float fexp(float s) {
    float t = s * 1.4426950408889634f;
    float z = t + 12582912.0f;
    int ii = __float_as_int(z);
    float r = t - (z - 12582912.0f);
    float p = 1.8775767e-3f;
    p = fmaf(p, r, 8.9893397e-3f);
    p = fmaf(p, r, 5.5826318e-2f);
    p = fmaf(p, r, 2.4015361e-1f);
    p = fmaf(p, r, 6.9315308e-1f);
    p = fmaf(p, r, 1.0f);
    return __int_as_float(__float_as_int(p) + (ii << 23));
}

#define LDM_X2(r_, a_)                                                         \
    asm volatile("ldmatrix.sync.aligned.m8n8.x2.shared.b16 {%0,%1}, [%2];"     \
                 : "=r"((r_)[0]), "=r"((r_)[1]) : "r"(a_))
#define LDM_X4(r_, a_)                                                         \
    asm volatile("ldmatrix.sync.aligned.m8n8.x4.shared.b16 {%0,%1,%2,%3}, [%4];" \
                 : "=r"((r_)[0]), "=r"((r_)[1]), "=r"((r_)[2]), "=r"((r_)[3]) : "r"(a_))
#define MMA_BF16(c_, a_, b_)                                                   \
    asm volatile("mma.sync.aligned.m16n8k16.row.col.f32.bf16.bf16.f32 "        \
                 "{%0,%1,%2,%3}, {%4,%5,%6,%7}, {%8,%9}, {%0,%1,%2,%3};"       \
                 : "+f"((c_)[0]), "+f"((c_)[1]), "+f"((c_)[2]), "+f"((c_)[3])  \
                 : "r"((a_)[0]), "r"((a_)[1]), "r"((a_)[2]), "r"((a_)[3]),     \
                   "r"((b_)[0]), "r"((b_)[1]))
#define CPA16(dst, src) \
    asm volatile("cp.async.ca.shared.global [%0], [%1], 16;" :: "r"(dst), "l"(src))
#define CPA_COMMIT() asm volatile("cp.async.commit_group;" ::: "memory")
#define CPA_WAIT0() asm volatile("cp.async.wait_group 0;" ::: "memory")
#define CPA_WAIT1() asm volatile("cp.async.wait_group 1;" ::: "memory")

// ---------------- 1. QKV projections (x+pos fused in, split-bf16 fused out) ----------------
__global__ void __launch_bounds__(256) k_qkv(
    const float* __restrict__ x, const float* __restrict__ pos,
    const float* __restrict__ Wq, const float* __restrict__ bq,
    const float* __restrict__ Wk, const float* __restrict__ bk,
    const float* __restrict__ Wv, const float* __restrict__ bv) {
    const int z = blockIdx.z;
    const float* W;
    const float* bias;
    float* out;
    if (z == 0)      { W = Wq; bias = bq; out = g_q; }
    else if (z == 1) { W = Wk; bias = bk; out = g_k; }
    else             { W = Wv; bias = bv; out = g_v; }

    __shared__ __align__(16) float AsT[32][68];   // [k][row]
    __shared__ __align__(16) float Bs2[32][68];   // [k][col]
    const int m0 = blockIdx.y * 64, n0 = blockIdx.x * 64;
    const int tid = threadIdx.x, tx = tid & 15, ty = tid >> 4;

    unsigned long long acc[4][2];
    #pragma unroll
    for (int i = 0; i < 4; i++) { acc[i][0] = 0ull; acc[i][1] = 0ull; }

    for (int kk = 0; kk < DD; kk += 32) {
        #pragma unroll
        for (int i = tid; i < 64 * 32; i += 256) {
            int r = i >> 5, c = i & 31;
            int gi = (m0 + r) * DD + kk + c;
            AsT[c][r] = x[gi] + pos[gi];
        }
        #pragma unroll
        for (int i = tid; i < 32 * 64; i += 256) {
            int r = i >> 6, c = i & 63;
            Bs2[r][c] = W[(kk + r) * DD + n0 + c];
        }
        __syncthreads();
        #pragma unroll 8
        for (int kq = 0; kq < 32; kq++) {
            float4 a = *(const float4*)&AsT[kq][ty * 4];
            ulonglong2 b = *(const ulonglong2*)&Bs2[kq][tx * 4];
            float av[4] = {a.x, a.y, a.z, a.w};
            #pragma unroll
            for (int r = 0; r < 4; r++) {
                unsigned long long ap;
                PACK2(ap, av[r], av[r]);
                FMA2(acc[r][0], ap, b.x);
                FMA2(acc[r][1], ap, b.y);
            }
        }
        __syncthreads();
    }

    __nv_bfloat16* sp = (z == 0) ? g_qs : g_ks;
    const float sc = (z == 0) ? 0.17677669529663687f : 1.0f;
    #pragma unroll
    for (int i = 0; i < 4; i++) {
        int row = m0 + ty * 4 + i;
        float v0, v1, v2, v3;
        UNPACK2(v0, v1, acc[i][0]);
        UNPACK2(v2, v3, acc[i][1]);
        float vv[4] = {v0, v1, v2, v3};
        #pragma unroll
        for (int j = 0; j < 4; j++) {
            int col = n0 + tx * 4 + j;
            int hh2 = col >> 5, dh = col & 31;
            float val = vv[j] + bias[col];
            out[((size_t)hh2 * NN + row) * DHH + dh] = val;
            if (z < 2) {
                float sv = val * sc;
                __nv_bfloat16 hi = __float2bfloat16(sv);
                size_t base = ((size_t)hh2 * NN + row) * 64 + dh;
                sp[base] = hi;
                sp[base + 32] = __float2bfloat16(sv - __bfloat162float(hi));
            }
        }
    }
}

// ---------------- 2. V^T hi/lo split ----------------
__global__ void k_split_vt() {
    int idx = blockIdx.x * 256 + threadIdx.x;     // h*NN+n
    int hh2 = idx >> 12, n = idx & 4095;
    const float* src = g_v + (size_t)idx * 32;
    #pragma unroll
    for (int d = 0; d < 32; d++) {
        float v = src[d];
        __nv_bfloat16 hi = __float2bfloat16(v);
        size_t o = (size_t)(hh2 * 32 + d) * NN + n;
        g_vth[o] = hi;
        g_vtl[o] = __float2bfloat16(v - __bfloat162float(hi));
    }
}

// ---------------- 3. CSR build + per-row dst sort ----------------
__global__ void k_zero() {
    int i = blockIdx.x * 256 + threadIdx.x;
    if (i < NN) { g_cnt[i] = 0; g_cur[i] = 0; }
}
__global__ void k_count(const int* __restrict__ ei) {
    int e = blockIdx.x * 256 + threadIdx.x;
    atomicAdd(&g_cnt[ei[e]], 1);
}
__global__ void __launch_bounds__(1024) k_scan() {
    __shared__ int sp[1024];
    int t = threadIdx.x;
    int c0 = g_cnt[4 * t], c1 = g_cnt[4 * t + 1], c2 = g_cnt[4 * t + 2], c3 = g_cnt[4 * t + 3];
    int s = c0 + c1 + c2 + c3;
    sp[t] = s;
    __syncthreads();
    for (int off = 1; off < 1024; off <<= 1) {
        int v = (t >= off) ? sp[t - off] : 0;
        __syncthreads();
        sp[t] += v;
        __syncthreads();
    }
    int base = sp[t] - s;
    g_off[4 * t] = base;
    g_off[4 * t + 1] = base + c0;
    g_off[4 * t + 2] = base + c0 + c1;
    g_off[4 * t + 3] = base + c0 + c1 + c2;
    if (t == 1023) g_off[NN] = sp[t];
}
__global__ void k_scatter(const int* __restrict__ ei, const int* __restrict__ et) {
    int e = blockIdx.x * 256 + threadIdx.x;
    int src = ei[e];
    int pos = g_off[src] + atomicAdd(&g_cur[src], 1);
    g_epack[pos] = ei[EE + e] | (et[e] << 12);
}
#define SCAP 80
__global__ void __launch_bounds__(128) k_sort() {
    __shared__ int buf[128][SCAP];
    int r = blockIdx.x * 128 + threadIdx.x;
    int s = g_off[r], e = g_off[r + 1];
    int n = e - s;
    if (n <= 1) return;
    if (n <= SCAP) {
        int* b = buf[threadIdx.x];
        for (int i = 0; i < n; i++) b[i] = g_epack[s + i];
        for (int i = 1; i < n; i++) {
            int key = b[i], kd = key & 0xFFF;
            int j = i - 1;
            while (j >= 0 && (b[j] & 0xFFF) > kd) { b[j + 1] = b[j]; j--; }
            b[j + 1] = key;
        }
        for (int i = 0; i < n; i++) g_epack[s + i] = b[i];
    } else {
        // fallback: in-place global insertion sort (statistically unreachable, but correct)
        for (int i = s + 1; i < e; i++) {
            int key = g_epack[i], kd = key & 0xFFF;
            int j = i - 1;
            while (j >= s && (g_epack[j] & 0xFFF) > kd) { g_epack[j + 1] = g_epack[j]; j--; }
            g_epack[j + 1] = key;
        }
    }
}

// ---------------- 4. dense attention via mma.sync, double-buffered cp.async ----------------
// grid (NN/128, HH), 256 threads (8 warps x 16 rows). O and l written unnormalized.
__global__ void __launch_bounds__(256, 2) k_flash3() {
    extern __shared__ char sm[];
    const uint32_t sb = s2u(sm);
    const int tid = threadIdx.x, w = tid >> 5, lane = tid & 31;
    const int h = blockIdx.y, m0 = blockIdx.x * 128;
    const int g = lane >> 2, c = lane & 3;

    // prologue: Q tile (plain stores) + tile 0 K/V via cp.async group 0
    {
        const uint4* qsrc = ((const uint4*)g_qs) + (size_t)(h * NN + m0) * 8;
        for (int t2 = tid; t2 < 1024; t2 += 256) {
            int r = t2 >> 3, u = t2 & 7;
            *(uint4*)(sm + OQ + r * 144 + u * 16) = qsrc[r * 8 + u];
        }
        const char* ksrc = (const char*)(g_ks + (size_t)(h * NN) * 64);
        for (int t2 = tid; t2 < 1024; t2 += 256) {
            int r = t2 >> 3, u = t2 & 7;
            CPA16(sb + OKB + r * 144 + u * 16, ksrc + (size_t)(r * 8 + u) * 16);
        }
        for (int t2 = tid; t2 < 512; t2 += 256) {
            int d = t2 >> 4, u = t2 & 15;
            size_t go = ((size_t)(h * 32 + d) * NN) * 2 + u * 16;
            CPA16(sb + OVB + d * 272 + u * 16, (const char*)g_vth + go);
            CPA16(sb + OVB + 8704 + d * 272 + u * 16, (const char*)g_vtl + go);
        }
        CPA_COMMIT();
        CPA_WAIT0();
    }
    __syncthreads();

    // persistent Q A-fragments: [Qh u0][Qh u1][Ql u0][Ql u1]
    uint32_t qf[4][4];
    {
        int r = (lane & 7) + ((lane >> 3) & 1) * 8;
        uint32_t base = sb + OQ + (w * 16 + r) * 144 + (lane >> 4) * 16;
        #pragma unroll
        for (int s = 0; s < 4; s++) LDM_X4(qf[s], base + s * 32);
    }

    float oacc[4][4];
    #pragma unroll
    for (int d = 0; d < 4; d++)
        #pragma unroll
        for (int i = 0; i < 4; i++) oacc[d][i] = 0.0f;
    float l0 = 0.0f, l1 = 0.0f;

    for (int t = 0; t < 32; t++) {
        __syncthreads();   // previous compute done; buffer (t+1)&1 reusable
        if (t + 1 < 32) {
            int jj = (t + 1) * 128, bi = (t + 1) & 1;
            const char* ksrc = (const char*)(g_ks + (size_t)(h * NN + jj) * 64);
            for (int t2 = tid; t2 < 1024; t2 += 256) {
                int r = t2 >> 3, u = t2 & 7;
                CPA16(sb + OKB + bi * 18432 + r * 144 + u * 16, ksrc + (size_t)(r * 8 + u) * 16);
            }
            for (int t2 = tid; t2 < 512; t2 += 256) {
                int d = t2 >> 4, u = t2 & 15;
                size_t go = ((size_t)(h * 32 + d) * NN + jj) * 2 + u * 16;
                CPA16(sb + OVB + bi * 17408 + d * 272 + u * 16, (const char*)g_vth + go);
                CPA16(sb + OVB + bi * 17408 + 8704 + d * 272 + u * 16, (const char*)g_vtl + go);
            }
            CPA_COMMIT();
            CPA_WAIT1();
        } else {
            CPA_WAIT0();
        }
        __syncthreads();   // tile t visible to all

        const int bi = t & 1;
        const uint32_t kbase = sb + OKB + bi * 18432 + (lane & 7) * 144 + ((lane >> 3) & 1) * 16;
        const uint32_t vbh = sb + OVB + bi * 17408 + (lane & 7) * 272 + ((lane >> 3) & 1) * 16;
        const uint32_t vbl = vbh + 8704;

        #pragma unroll 1
        for (int kg = 0; kg < 8; kg++) {
            float sa[4] = {0.f, 0.f, 0.f, 0.f};
            float sbv[4] = {0.f, 0.f, 0.f, 0.f};
            uint32_t b0[2], b1[2];
            uint32_t ka0 = kbase + (2 * kg) * (8 * 144);
            uint32_t ka1 = kbase + (2 * kg + 1) * (8 * 144);
            LDM_X2(b0, ka0);        LDM_X2(b1, ka0 + 32);
            MMA_BF16(sa, qf[0], b0); MMA_BF16(sa, qf[1], b1);
            MMA_BF16(sa, qf[2], b0); MMA_BF16(sa, qf[3], b1);
            LDM_X2(b0, ka0 + 64);   LDM_X2(b1, ka0 + 96);
            MMA_BF16(sa, qf[0], b0); MMA_BF16(sa, qf[1], b1);
            LDM_X2(b0, ka1);        LDM_X2(b1, ka1 + 32);
            MMA_BF16(sbv, qf[0], b0); MMA_BF16(sbv, qf[1], b1);
            MMA_BF16(sbv, qf[2], b0); MMA_BF16(sbv, qf[3], b1);
            LDM_X2(b0, ka1 + 64);   LDM_X2(b1, ka1 + 96);
            MMA_BF16(sbv, qf[0], b0); MMA_BF16(sbv, qf[1], b1);

            #pragma unroll
            for (int i = 0; i < 4; i++) { sa[i] = fexp(sa[i]); sbv[i] = fexp(sbv[i]); }
            l0 += sa[0] + sa[1] + sbv[0] + sbv[1];
            l1 += sa[2] + sa[3] + sbv[2] + sbv[3];

            uint32_t ah[4], al[4];
            asm("cvt.rn.bf16x2.f32 %0, %1, %2;" : "=r"(ah[0]) : "f"(sa[1]), "f"(sa[0]));
            asm("cvt.rn.bf16x2.f32 %0, %1, %2;" : "=r"(ah[1]) : "f"(sa[3]), "f"(sa[2]));
            asm("cvt.rn.bf16x2.f32 %0, %1, %2;" : "=r"(ah[2]) : "f"(sbv[1]), "f"(sbv[0]));
            asm("cvt.rn.bf16x2.f32 %0, %1, %2;" : "=r"(ah[3]) : "f"(sbv[3]), "f"(sbv[2]));
            #pragma unroll
            for (int i = 0; i < 2; i++) {
                float e0 = (i ? sbv[0] : sa[0]), e1 = (i ? sbv[1] : sa[1]);
                float e2 = (i ? sbv[2] : sa[2]), e3 = (i ? sbv[3] : sa[3]);
                uint32_t h01 = ah[i * 2], h23 = ah[i * 2 + 1];
                float r0 = __uint_as_float(h01 << 16);
                float r1 = __uint_as_float(h01 & 0xFFFF0000u);
                float r2 = __uint_as_float(h23 << 16);
                float r3 = __uint_as_float(h23 & 0xFFFF0000u);
                asm("cvt.rn.bf16x2.f32 %0, %1, %2;" : "=r"(al[i * 2]) : "f"(e1 - r1), "f"(e0 - r0));
                asm("cvt.rn.bf16x2.f32 %0, %1, %2;" : "=r"(al[i * 2 + 1]) : "f"(e3 - r3), "f"(e2 - r2));
            }

            #pragma unroll
            for (int d = 0; d < 4; d++) {
                uint32_t vh[2], vl[2];
                LDM_X2(vh, vbh + d * (8 * 272) + kg * 32);
                LDM_X2(vl, vbl + d * (8 * 272) + kg * 32);
                MMA_BF16(oacc[d], ah, vh);
                MMA_BF16(oacc[d], ah, vl);
                MMA_BF16(oacc[d], al, vh);
            }
        }
    }

    l0 += __shfl_xor_sync(0xffffffffu, l0, 1);
    l0 += __shfl_xor_sync(0xffffffffu, l0, 2);
    l1 += __shfl_xor_sync(0xffffffffu, l1, 1);
    l1 += __shfl_xor_sync(0xffffffffu, l1, 2);
    int row0 = m0 + w * 16 + g;
    if (c == 0) {
        g_l[h * NN + row0] = l0;
        g_l[h * NN + row0 + 8] = l1;
    }
    float* o0 = g_att + (size_t)row0 * DD + h * 32;
    float* o1 = g_att + (size_t)(row0 + 8) * DD + h * 32;
    #pragma unroll
    for (int d = 0; d < 4; d++) {
        *(float2*)(o0 + d * 8 + 2 * c) = make_float2(oacc[d][0], oacc[d][1]);
        *(float2*)(o1 + d * 8 + 2 * c) = make_float2(oacc[d][2], oacc[d][3]);
    }
}

// ---------------- 5. sparse edge-bias correction ----------------
__global__ void __launch_bounds__(256) k_corr(const float* __restrict__ emb) {
    int t = blockIdx.x * 256 + threadIdx.x;
    int row = t >> 3, h = t & 7;
    int e = g_off[row], end = g_off[row + 1];
    if (e >= end) return;

    const float* qp = g_q + ((size_t)h * NN + row) * 32;
    float4 qv[8];
    #pragma unroll
    for (int i = 0; i < 8; i++) qv[i] = ((const float4*)qp)[i];
    const float* kh_ = g_k + (size_t)h * NN * 32;
    const float* vh_ = g_v + (size_t)h * NN * 32;

    float4 oa[8];
    #pragma unroll
    for (int i = 0; i < 8; i++) oa[i] = make_float4(0.f, 0.f, 0.f, 0.f);
    float lacc = 0.0f;
    const float scale = 0.17677669529663687f;

    while (e < end) {
        int pk = g_epack[e];
        int d = pk & 0xFFF;
        float bs = emb[(pk >> 12) * HH + h];
        e++;
        while (e < end && (g_epack[e] & 0xFFF) == d) {
            bs += emb[(g_epack[e] >> 12) * HH + h];
            e++;
        }
        const float4* kp = (const float4*)(kh_ + (size_t)d * 32);
        float s = 0.0f;
        #pragma unroll
        for (int i = 0; i < 8; i++) {
            float4 kk = kp[i];
            s += qv[i].x * kk.x + qv[i].y * kk.y + qv[i].z * kk.z + qv[i].w * kk.w;
        }
        float wgt = __expf(s * scale) * (__expf(bs) - 1.0f);
        lacc += wgt;
        const float4* vp = (const float4*)(vh_ + (size_t)d * 32);
        #pragma unroll
        for (int i = 0; i < 8; i++) {
            float4 vv = vp[i];
            oa[i].x += wgt * vv.x; oa[i].y += wgt * vv.y;
            oa[i].z += wgt * vv.z; oa[i].w += wgt * vv.w;
        }
    }

    g_l[h * NN + row] += lacc;
    float* dst = g_att + (size_t)row * DD + h * 32;
    #pragma unroll
    for (int i = 0; i < 8; i++) {
        float4 cur = ((float4*)dst)[i];
        ((float4*)dst)[i] = make_float4(cur.x + oa[i].x, cur.y + oa[i].y,
                                        cur.z + oa[i].z, cur.w + oa[i].w);
    }
}

// ---------------- 6. tmp = x + (att/l) @ Wo + bo  (normalization fused) ----------------
__global__ void __launch_bounds__(256) k_oproj(const float* __restrict__ Wo,
                                               const float* __restrict__ bo,
                                               const float* __restrict__ x) {
    __shared__ __align__(16) float AsT[32][68];
    __shared__ __align__(16) float Bs2[32][68];
    __shared__ float invl[64][8];
    const int m0 = blockIdx.y * 64, n0 = blockIdx.x * 64;
    const int tid = threadIdx.x, tx = tid & 15, ty = tid >> 4;

    #pragma unroll
    for (int i = tid; i < 512; i += 256) {
        int r = i >> 3, hh2 = i & 7;
        invl[r][hh2] = 1.0f / g_l[hh2 * NN + m0 + r];
    }
    __syncthreads();

    unsigned long long acc[4][2];
    #pragma unroll
    for (int i = 0; i < 4; i++) { acc[i][0] = 0ull; acc[i][1] = 0ull; }

    for (int kk = 0; kk < DD; kk += 32) {
        #pragma unroll
        for (int i = tid; i < 64 * 32; i += 256) {
            int r = i >> 5, c = i & 31;
            AsT[c][r] = g_att[(m0 + r) * DD + kk + c] * invl[r][(kk + c) >> 5];
        }
        #pragma unroll
        for (int i = tid; i < 32 * 64; i += 256) {
            int r = i >> 6, c = i & 63;
            Bs2[r][c] = Wo[(kk + r) * DD + n0 + c];
        }
        __syncthreads();
        #pragma unroll 8
        for (int kq = 0; kq < 32; kq++) {
            float4 a = *(const float4*)&AsT[kq][ty * 4];
            ulonglong2 b = *(const ulonglong2*)&Bs2[kq][tx * 4];
            float av[4] = {a.x, a.y, a.z, a.w};
            #pragma unroll
            for (int r = 0; r < 4; r++) {
                unsigned long long ap;
                PACK2(ap, av[r], av[r]);
                FMA2(acc[r][0], ap, b.x);
                FMA2(acc[r][1], ap, b.y);
            }
        }
        __syncthreads();
    }
    #pragma unroll
    for (int i = 0; i < 4; i++) {
        int row = m0 + ty * 4 + i;
        float v0, v1, v2, v3;
        UNPACK2(v0, v1, acc[i][0]);
        UNPACK2(v2, v3, acc[i][1]);
        float vv[4] = {v0, v1, v2, v3};
        #pragma unroll
        for (int j = 0; j < 4; j++) {
            int col = n0 + tx * 4 + j;
            g_tmp[(size_t)row * DD + col] = vv[j] + bo[col] + x[(size_t)row * DD + col];
        }
    }
}

// ---------------- 7. LayerNorm ----------------
__global__ void __launch_bounds__(256) k_ln(const float* __restrict__ gamma,
                                            const float* __restrict__ beta,
                                            float* __restrict__ out) {
    const int n = blockIdx.x, tid = threadIdx.x;
    float v = g_tmp[(size_t)n * DD + tid];
    __shared__ float red[8];
    float s = v;
    #pragma unroll
    for (int o = 16; o > 0; o >>= 1) s += __shfl_xor_sync(0xffffffffu, s, o);
    if ((tid & 31) == 0) red[tid >> 5] = s;
    __syncthreads();
    float tot = 0.f;
    #pragma unroll
    for (int i = 0; i < 8; i++) tot += red[i];
    float mu = tot * (1.0f / DD);
    float d = v - mu;
    __syncthreads();
    float sq = d * d;
    #pragma unroll
    for (int o = 16; o > 0; o >>= 1) sq += __shfl_xor_sync(0xffffffffu, sq, o);
    if ((tid & 31) == 0) red[tid >> 5] = sq;
    __syncthreads();
    float tot2 = 0.f;
    #pragma unroll
    for (int i = 0; i < 8; i++) tot2 += red[i];
    float var = tot2 * (1.0f / DD);
    out[(size_t)n * DD + tid] = d * rsqrtf(var + 1e-5f) * gamma[tid] + beta[tid];
}

// ---------------- launch ----------------
extern "C" void kernel_launch(void* const* d_in, const int* in_sizes, int n_in,
                              void* d_out, int out_size) {
    const float* x       = (const float*)d_in[0];
    const float* pos     = (const float*)d_in[1];
    const int* ei        = (const int*)d_in[2];
    const int* et        = (const int*)d_in[3];
    const float* Wq = (const float*)d_in[4];
    const float* bq = (const float*)d_in[5];
    const float* Wk = (const float*)d_in[6];
    const float* bk = (const float*)d_in[7];
    const float* Wv = (const float*)d_in[8];
    const float* bv = (const float*)d_in[9];
    const float* Wo = (const float*)d_in[10];
    const float* bo = (const float*)d_in[11];
    const float* emb   = (const float*)d_in[12];
    const float* gamma = (const float*)d_in[13];
    const float* beta  = (const float*)d_in[14];
    float* out = (float*)d_out;

    cudaFuncSetAttribute(k_flash3, cudaFuncAttributeMaxDynamicSharedMemorySize, SM3);

    k_qkv<<<dim3(DD / 64, NN / 64, 3), 256>>>(x, pos, Wq, bq, Wk, bk, Wv, bv);
    k_split_vt<<<HH * NN / 256, 256>>>();
    k_zero<<<(NN + 255) / 256, 256>>>();
    k_count<<<EE / 256, 256>>>(ei);
    k_scan<<<1, 1024>>>();
    k_scatter<<<EE / 256, 256>>>(ei, et);
    k_sort<<<NN / 128, 128>>>();
    k_flash3<<<dim3(NN / 128, HH), 256, SM3>>>();
    k_corr<<<(NN * HH) / 256, 256>>>(emb);
    k_oproj<<<dim3(DD / 64, NN / 64), 256>>>(Wo, bo, x);
    k_ln<<<NN, 256>>>(gamma, beta, out);
}

// round 12
// speedup vs baseline: 3.8133x; 1.1268x over previous
#include <cuda_runtime.h>
#include <cuda_bf16.h>
#include <cstdint>

#define NN 4096
#define DD 256
#define HH 8
#define DHH 32
#define EE 131072

// ---------------- scratch ----------------
__device__ float g_q[HH * NN * DHH];
__device__ float g_k[HH * NN * DHH];
__device__ float g_v[HH * NN * DHH];
__device__ float g_att[NN * DD];      // unnormalized attn out
__device__ float g_l[HH * NN];        // row sums
__device__ float g_tmp[NN * DD];
// CSR of edges keyed by source row (sorted by dst within row)
__device__ int g_cnt[NN];
__device__ int g_cur[NN];
__device__ int g_off[NN + 1];
__device__ int g_epack[EE];           // dst | (type<<12)
// split-bf16 operands
__device__ __nv_bfloat16 g_qs[HH * NN * 64];   // per row: [hi 32][lo 32], q pre-scaled
__device__ __nv_bfloat16 g_ks[HH * NN * 64];
__device__ __nv_bfloat16 g_vth[HH * 32 * NN];  // V^T hi  [h][d][n]
__device__ __nv_bfloat16 g_vtl[HH * 32 * NN];  // V^T lo

// ---------------- flash3 smem layout (dynamic, double-buffered K/V) ----------------
#define OQ    0
#define OKB   18432                 // K bufs: +bi*18432  (128 x 144B)
#define OVB   55296                 // V bufs: +bi*17408; hi at +0, lo at +8704 (32 x 272B)
#define SM3   90112

// ---------------- packed fp32x2 helpers ----------------
#define PACK2(u, lo, hi) asm("mov.b64 %0, {%1,%2};" : "=l"(u) : "f"(lo), "f"(hi))
#define UNPACK2(lo, hi, u) asm("mov.b64 {%0,%1}, %2;" : "=f"(lo), "=f"(hi) : "l"(u))
#define FMA2(d, a, b) asm("fma.rn.f32x2 %0, %1, %2, %0;" : "+l"(d) : "l"(a), "l"(b))

__device__ __forceinline__ uint32_t s2u(const void* p) {
    uint32_t a;
    asm("{ .reg .u64 t; cvta.to.shared.u64 t, %1; cvt.u32.u64 %0, t; }" : "=r"(a) : "l"(p));
    return a;
}

// exp via MUFU pipe (overlaps with FMA + tensor pipes)
__device__ __forceinline__ float mexp(float s) {
    float r;
    asm("ex2.approx.f32 %0, %1;" : "=f"(r) : "f"(s * 1.4426950408889634f));
    return r;
}

#define LDM_X2(r_, a_)                                                         \
    asm volatile("ldmatrix.sync.aligned.m8n8.x2.shared.b16 {%0,%1}, [%2];"     \
                 : "=r"((r_)[0]), "=r"((r_)[1]) : "r"(a_))
#define LDM_X4(r_, a_)                                                         \
    asm volatile("ldmatrix.sync.aligned.m8n8.x4.shared.b16 {%0,%1,%2,%3}, [%4];" \
                 : "=r"((r_)[0]), "=r"((r_)[1]), "=r"((r_)[2]), "=r"((r_)[3]) : "r"(a_))
#define MMA_BF16(c_, a_, b_)                                                   \
    asm volatile("mma.sync.aligned.m16n8k16.row.col.f32.bf16.bf16.f32 "        \
                 "{%0,%1,%2,%3}, {%4,%5,%6,%7}, {%8,%9}, {%0,%1,%2,%3};"       \
                 : "+f"((c_)[0]), "+f"((c_)[1]), "+f"((c_)[2]), "+f"((c_)[3])  \
                 : "r"((a_)[0]), "r"((a_)[1]), "r"((a_)[2]), "r"((a_)[3]),     \
                   "r"((b_)[0]), "r"((b_)[1]))
#define CPA16(dst, src) \
    asm volatile("cp.async.ca.shared.global [%0], [%1], 16;" :: "r"(dst), "l"(src))
#define CPA_COMMIT() asm volatile("cp.async.commit_group;" ::: "memory")
#define CPA_WAIT0() asm volatile("cp.async.wait_group 0;" ::: "memory")
#define CPA_WAIT1() asm volatile("cp.async.wait_group 1;" ::: "memory")

// ---------------- 1. QKV projections (x+pos fused in, split-bf16 fused out) ----------------
__global__ void __launch_bounds__(256) k_qkv(
    const float* __restrict__ x, const float* __restrict__ pos,
    const float* __restrict__ Wq, const float* __restrict__ bq,
    const float* __restrict__ Wk, const float* __restrict__ bk,
    const float* __restrict__ Wv, const float* __restrict__ bv) {
    const int z = blockIdx.z;
    const float* W;
    const float* bias;
    float* out;
    if (z == 0)      { W = Wq; bias = bq; out = g_q; }
    else if (z == 1) { W = Wk; bias = bk; out = g_k; }
    else             { W = Wv; bias = bv; out = g_v; }

    __shared__ __align__(16) float AsT[32][68];   // [k][row]
    __shared__ __align__(16) float Bs2[32][68];   // [k][col]
    const int m0 = blockIdx.y * 64, n0 = blockIdx.x * 64;
    const int tid = threadIdx.x, tx = tid & 15, ty = tid >> 4;

    unsigned long long acc[4][2];
    #pragma unroll
    for (int i = 0; i < 4; i++) { acc[i][0] = 0ull; acc[i][1] = 0ull; }

    for (int kk = 0; kk < DD; kk += 32) {
        #pragma unroll
        for (int i = tid; i < 64 * 32; i += 256) {
            int r = i >> 5, c = i & 31;
            int gi = (m0 + r) * DD + kk + c;
            AsT[c][r] = x[gi] + pos[gi];
        }
        #pragma unroll
        for (int i = tid; i < 32 * 64; i += 256) {
            int r = i >> 6, c = i & 63;
            Bs2[r][c] = W[(kk + r) * DD + n0 + c];
        }
        __syncthreads();
        #pragma unroll 8
        for (int kq = 0; kq < 32; kq++) {
            float4 a = *(const float4*)&AsT[kq][ty * 4];
            ulonglong2 b = *(const ulonglong2*)&Bs2[kq][tx * 4];
            float av[4] = {a.x, a.y, a.z, a.w};
            #pragma unroll
            for (int r = 0; r < 4; r++) {
                unsigned long long ap;
                PACK2(ap, av[r], av[r]);
                FMA2(acc[r][0], ap, b.x);
                FMA2(acc[r][1], ap, b.y);
            }
        }
        __syncthreads();
    }

    __nv_bfloat16* sp = (z == 0) ? g_qs : g_ks;
    const float sc = (z == 0) ? 0.17677669529663687f : 1.0f;
    #pragma unroll
    for (int i = 0; i < 4; i++) {
        int row = m0 + ty * 4 + i;
        float v0, v1, v2, v3;
        UNPACK2(v0, v1, acc[i][0]);
        UNPACK2(v2, v3, acc[i][1]);
        float vv[4] = {v0, v1, v2, v3};
        #pragma unroll
        for (int j = 0; j < 4; j++) {
            int col = n0 + tx * 4 + j;
            int hh2 = col >> 5, dh = col & 31;
            float val = vv[j] + bias[col];
            out[((size_t)hh2 * NN + row) * DHH + dh] = val;
            if (z < 2) {
                float sv = val * sc;
                __nv_bfloat16 hi = __float2bfloat16(sv);
                size_t base = ((size_t)hh2 * NN + row) * 64 + dh;
                sp[base] = hi;
                sp[base + 32] = __float2bfloat16(sv - __bfloat162float(hi));
            }
        }
    }
}

// ---------------- 2. V^T hi/lo split ----------------
__global__ void k_split_vt() {
    int idx = blockIdx.x * 256 + threadIdx.x;     // h*NN+n
    int hh2 = idx >> 12, n = idx & 4095;
    const float* src = g_v + (size_t)idx * 32;
    #pragma unroll
    for (int d = 0; d < 32; d++) {
        float v = src[d];
        __nv_bfloat16 hi = __float2bfloat16(v);
        size_t o = (size_t)(hh2 * 32 + d) * NN + n;
        g_vth[o] = hi;
        g_vtl[o] = __float2bfloat16(v - __bfloat162float(hi));
    }
}

// ---------------- 3. CSR build + per-row dst sort ----------------
__global__ void k_zero() {
    int i = blockIdx.x * 256 + threadIdx.x;
    if (i < NN) { g_cnt[i] = 0; g_cur[i] = 0; }
}
__global__ void k_count(const int* __restrict__ ei) {
    int e = blockIdx.x * 256 + threadIdx.x;
    atomicAdd(&g_cnt[ei[e]], 1);
}
__global__ void __launch_bounds__(1024) k_scan() {
    __shared__ int sp[1024];
    int t = threadIdx.x;
    int c0 = g_cnt[4 * t], c1 = g_cnt[4 * t + 1], c2 = g_cnt[4 * t + 2], c3 = g_cnt[4 * t + 3];
    int s = c0 + c1 + c2 + c3;
    sp[t] = s;
    __syncthreads();
    for (int off = 1; off < 1024; off <<= 1) {
        int v = (t >= off) ? sp[t - off] : 0;
        __syncthreads();
        sp[t] += v;
        __syncthreads();
    }
    int base = sp[t] - s;
    g_off[4 * t] = base;
    g_off[4 * t + 1] = base + c0;
    g_off[4 * t + 2] = base + c0 + c1;
    g_off[4 * t + 3] = base + c0 + c1 + c2;
    if (t == 1023) g_off[NN] = sp[t];
}
__global__ void k_scatter(const int* __restrict__ ei, const int* __restrict__ et) {
    int e = blockIdx.x * 256 + threadIdx.x;
    int src = ei[e];
    int pos = g_off[src] + atomicAdd(&g_cur[src], 1);
    g_epack[pos] = ei[EE + e] | (et[e] << 12);
}
#define SCAP 80
__global__ void __launch_bounds__(128) k_sort() {
    __shared__ int buf[128][SCAP];
    int r = blockIdx.x * 128 + threadIdx.x;
    int s = g_off[r], e = g_off[r + 1];
    int n = e - s;
    if (n <= 1) return;
    if (n <= SCAP) {
        int* b = buf[threadIdx.x];
        for (int i = 0; i < n; i++) b[i] = g_epack[s + i];
        for (int i = 1; i < n; i++) {
            int key = b[i], kd = key & 0xFFF;
            int j = i - 1;
            while (j >= 0 && (b[j] & 0xFFF) > kd) { b[j + 1] = b[j]; j--; }
            b[j + 1] = key;
        }
        for (int i = 0; i < n; i++) g_epack[s + i] = b[i];
    } else {
        for (int i = s + 1; i < e; i++) {
            int key = g_epack[i], kd = key & 0xFFF;
            int j = i - 1;
            while (j >= s && (g_epack[j] & 0xFFF) > kd) { g_epack[j + 1] = g_epack[j]; j--; }
            g_epack[j + 1] = key;
        }
    }
}

// ---------------- 4. dense attention via mma.sync, double-buffered cp.async ----------------
// grid (NN/128, HH), 256 threads (8 warps x 16 rows). O and l written unnormalized.
__global__ void __launch_bounds__(256, 2) k_flash3() {
    extern __shared__ char sm[];
    const uint32_t sb = s2u(sm);
    const int tid = threadIdx.x, w = tid >> 5, lane = tid & 31;
    const int h = blockIdx.y, m0 = blockIdx.x * 128;
    const int g = lane >> 2, c = lane & 3;

    // prologue: Q tile (plain stores) + tile 0 K/V via cp.async group 0
    {
        const uint4* qsrc = ((const uint4*)g_qs) + (size_t)(h * NN + m0) * 8;
        for (int t2 = tid; t2 < 1024; t2 += 256) {
            int r = t2 >> 3, u = t2 & 7;
            *(uint4*)(sm + OQ + r * 144 + u * 16) = qsrc[r * 8 + u];
        }
        const char* ksrc = (const char*)(g_ks + (size_t)(h * NN) * 64);
        for (int t2 = tid; t2 < 1024; t2 += 256) {
            int r = t2 >> 3, u = t2 & 7;
            CPA16(sb + OKB + r * 144 + u * 16, ksrc + (size_t)(r * 8 + u) * 16);
        }
        for (int t2 = tid; t2 < 512; t2 += 256) {
            int d = t2 >> 4, u = t2 & 15;
            size_t go = ((size_t)(h * 32 + d) * NN) * 2 + u * 16;
            CPA16(sb + OVB + d * 272 + u * 16, (const char*)g_vth + go);
            CPA16(sb + OVB + 8704 + d * 272 + u * 16, (const char*)g_vtl + go);
        }
        CPA_COMMIT();
        CPA_WAIT0();
    }
    __syncthreads();

    // persistent Q A-fragments: [Qh u0][Qh u1][Ql u0][Ql u1]
    uint32_t qf[4][4];
    {
        int r = (lane & 7) + ((lane >> 3) & 1) * 8;
        uint32_t base = sb + OQ + (w * 16 + r) * 144 + (lane >> 4) * 16;
        #pragma unroll
        for (int s = 0; s < 4; s++) LDM_X4(qf[s], base + s * 32);
    }

    float oacc[4][4];
    #pragma unroll
    for (int d = 0; d < 4; d++)
        #pragma unroll
        for (int i = 0; i < 4; i++) oacc[d][i] = 0.0f;
    float l0 = 0.0f, l1 = 0.0f;

    for (int t = 0; t < 32; t++) {
        __syncthreads();
        if (t + 1 < 32) {
            int jj = (t + 1) * 128, bi = (t + 1) & 1;
            const char* ksrc = (const char*)(g_ks + (size_t)(h * NN + jj) * 64);
            for (int t2 = tid; t2 < 1024; t2 += 256) {
                int r = t2 >> 3, u = t2 & 7;
                CPA16(sb + OKB + bi * 18432 + r * 144 + u * 16, ksrc + (size_t)(r * 8 + u) * 16);
            }
            for (int t2 = tid; t2 < 512; t2 += 256) {
                int d = t2 >> 4, u = t2 & 15;
                size_t go = ((size_t)(h * 32 + d) * NN + jj) * 2 + u * 16;
                CPA16(sb + OVB + bi * 17408 + d * 272 + u * 16, (const char*)g_vth + go);
                CPA16(sb + OVB + bi * 17408 + 8704 + d * 272 + u * 16, (const char*)g_vtl + go);
            }
            CPA_COMMIT();
            CPA_WAIT1();
        } else {
            CPA_WAIT0();
        }
        __syncthreads();

        const int bi = t & 1;
        const uint32_t kbase = sb + OKB + bi * 18432 + (lane & 7) * 144 + ((lane >> 3) & 1) * 16;
        const uint32_t vbh = sb + OVB + bi * 17408 + (lane & 7) * 272 + ((lane >> 3) & 1) * 16;
        const uint32_t vbl = vbh + 8704;

        #pragma unroll 1
        for (int kg = 0; kg < 8; kg++) {
            float sa[4] = {0.f, 0.f, 0.f, 0.f};
            float sbv[4] = {0.f, 0.f, 0.f, 0.f};
            uint32_t b0[2], b1[2];
            uint32_t ka0 = kbase + (2 * kg) * (8 * 144);
            uint32_t ka1 = kbase + (2 * kg + 1) * (8 * 144);
            LDM_X2(b0, ka0);        LDM_X2(b1, ka0 + 32);
            MMA_BF16(sa, qf[0], b0); MMA_BF16(sa, qf[1], b1);
            MMA_BF16(sa, qf[2], b0); MMA_BF16(sa, qf[3], b1);
            LDM_X2(b0, ka0 + 64);   LDM_X2(b1, ka0 + 96);
            MMA_BF16(sa, qf[0], b0); MMA_BF16(sa, qf[1], b1);
            LDM_X2(b0, ka1);        LDM_X2(b1, ka1 + 32);
            MMA_BF16(sbv, qf[0], b0); MMA_BF16(sbv, qf[1], b1);
            MMA_BF16(sbv, qf[2], b0); MMA_BF16(sbv, qf[3], b1);
            LDM_X2(b0, ka1 + 64);   LDM_X2(b1, ka1 + 96);
            MMA_BF16(sbv, qf[0], b0); MMA_BF16(sbv, qf[1], b1);

            // exp on the MUFU pipe (overlaps tensor + FMA work)
            #pragma unroll
            for (int i = 0; i < 4; i++) { sa[i] = mexp(sa[i]); sbv[i] = mexp(sbv[i]); }
            l0 += sa[0] + sa[1] + sbv[0] + sbv[1];
            l1 += sa[2] + sa[3] + sbv[2] + sbv[3];

            // P in bf16 (hi only; lo term contributes ~1e-4 rel — dropped)
            uint32_t ah[4];
            asm("cvt.rn.bf16x2.f32 %0, %1, %2;" : "=r"(ah[0]) : "f"(sa[1]), "f"(sa[0]));
            asm("cvt.rn.bf16x2.f32 %0, %1, %2;" : "=r"(ah[1]) : "f"(sa[3]), "f"(sa[2]));
            asm("cvt.rn.bf16x2.f32 %0, %1, %2;" : "=r"(ah[2]) : "f"(sbv[1]), "f"(sbv[0]));
            asm("cvt.rn.bf16x2.f32 %0, %1, %2;" : "=r"(ah[3]) : "f"(sbv[3]), "f"(sbv[2]));

            #pragma unroll
            for (int d = 0; d < 4; d++) {
                uint32_t vh[2], vl[2];
                LDM_X2(vh, vbh + d * (8 * 272) + kg * 32);
                LDM_X2(vl, vbl + d * (8 * 272) + kg * 32);
                MMA_BF16(oacc[d], ah, vh);
                MMA_BF16(oacc[d], ah, vl);
            }
        }
    }

    l0 += __shfl_xor_sync(0xffffffffu, l0, 1);
    l0 += __shfl_xor_sync(0xffffffffu, l0, 2);
    l1 += __shfl_xor_sync(0xffffffffu, l1, 1);
    l1 += __shfl_xor_sync(0xffffffffu, l1, 2);
    int row0 = m0 + w * 16 + g;
    if (c == 0) {
        g_l[h * NN + row0] = l0;
        g_l[h * NN + row0 + 8] = l1;
    }
    float* o0 = g_att + (size_t)row0 * DD + h * 32;
    float* o1 = g_att + (size_t)(row0 + 8) * DD + h * 32;
    #pragma unroll
    for (int d = 0; d < 4; d++) {
        *(float2*)(o0 + d * 8 + 2 * c) = make_float2(oacc[d][0], oacc[d][1]);
        *(float2*)(o1 + d * 8 + 2 * c) = make_float2(oacc[d][2], oacc[d][3]);
    }
}

// ---------------- 5. sparse edge-bias correction ----------------
__global__ void __launch_bounds__(256) k_corr(const float* __restrict__ emb) {
    int t = blockIdx.x * 256 + threadIdx.x;
    int row = t >> 3, h = t & 7;
    int e = g_off[row], end = g_off[row + 1];
    if (e >= end) return;

    const float* qp = g_q + ((size_t)h * NN + row) * 32;
    float4 qv[8];
    #pragma unroll
    for (int i = 0; i < 8; i++) qv[i] = ((const float4*)qp)[i];
    const float* kh_ = g_k + (size_t)h * NN * 32;
    const float* vh_ = g_v + (size_t)h * NN * 32;

    float4 oa[8];
    #pragma unroll
    for (int i = 0; i < 8; i++) oa[i] = make_float4(0.f, 0.f, 0.f, 0.f);
    float lacc = 0.0f;
    const float scale = 0.17677669529663687f;

    while (e < end) {
        int pk = g_epack[e];
        int d = pk & 0xFFF;
        float bs = emb[(pk >> 12) * HH + h];
        e++;
        while (e < end && (g_epack[e] & 0xFFF) == d) {
            bs += emb[(g_epack[e] >> 12) * HH + h];
            e++;
        }
        const float4* kp = (const float4*)(kh_ + (size_t)d * 32);
        float s = 0.0f;
        #pragma unroll
        for (int i = 0; i < 8; i++) {
            float4 kk = kp[i];
            s += qv[i].x * kk.x + qv[i].y * kk.y + qv[i].z * kk.z + qv[i].w * kk.w;
        }
        float wgt = __expf(s * scale) * (__expf(bs) - 1.0f);
        lacc += wgt;
        const float4* vp = (const float4*)(vh_ + (size_t)d * 32);
        #pragma unroll
        for (int i = 0; i < 8; i++) {
            float4 vv = vp[i];
            oa[i].x += wgt * vv.x; oa[i].y += wgt * vv.y;
            oa[i].z += wgt * vv.z; oa[i].w += wgt * vv.w;
        }
    }

    g_l[h * NN + row] += lacc;
    float* dst = g_att + (size_t)row * DD + h * 32;
    #pragma unroll
    for (int i = 0; i < 8; i++) {
        float4 cur = ((float4*)dst)[i];
        ((float4*)dst)[i] = make_float4(cur.x + oa[i].x, cur.y + oa[i].y,
                                        cur.z + oa[i].z, cur.w + oa[i].w);
    }
}

// ---------------- 6. tmp = x + (att/l) @ Wo + bo  (normalization fused) ----------------
__global__ void __launch_bounds__(256) k_oproj(const float* __restrict__ Wo,
                                               const float* __restrict__ bo,
                                               const float* __restrict__ x) {
    __shared__ __align__(16) float AsT[32][68];
    __shared__ __align__(16) float Bs2[32][68];
    __shared__ float invl[64][8];
    const int m0 = blockIdx.y * 64, n0 = blockIdx.x * 64;
    const int tid = threadIdx.x, tx = tid & 15, ty = tid >> 4;

    #pragma unroll
    for (int i = tid; i < 512; i += 256) {
        int r = i >> 3, hh2 = i & 7;
        invl[r][hh2] = 1.0f / g_l[hh2 * NN + m0 + r];
    }
    __syncthreads();

    unsigned long long acc[4][2];
    #pragma unroll
    for (int i = 0; i < 4; i++) { acc[i][0] = 0ull; acc[i][1] = 0ull; }

    for (int kk = 0; kk < DD; kk += 32) {
        #pragma unroll
        for (int i = tid; i < 64 * 32; i += 256) {
            int r = i >> 5, c = i & 31;
            AsT[c][r] = g_att[(m0 + r) * DD + kk + c] * invl[r][(kk + c) >> 5];
        }
        #pragma unroll
        for (int i = tid; i < 32 * 64; i += 256) {
            int r = i >> 6, c = i & 63;
            Bs2[r][c] = Wo[(kk + r) * DD + n0 + c];
        }
        __syncthreads();
        #pragma unroll 8
        for (int kq = 0; kq < 32; kq++) {
            float4 a = *(const float4*)&AsT[kq][ty * 4];
            ulonglong2 b = *(const ulonglong2*)&Bs2[kq][tx * 4];
            float av[4] = {a.x, a.y, a.z, a.w};
            #pragma unroll
            for (int r = 0; r < 4; r++) {
                unsigned long long ap;
                PACK2(ap, av[r], av[r]);
                FMA2(acc[r][0], ap, b.x);
                FMA2(acc[r][1], ap, b.y);
            }
        }
        __syncthreads();
    }
    #pragma unroll
    for (int i = 0; i < 4; i++) {
        int row = m0 + ty * 4 + i;
        float v0, v1, v2, v3;
        UNPACK2(v0, v1, acc[i][0]);
        UNPACK2(v2, v3, acc[i][1]);
        float vv[4] = {v0, v1, v2, v3};
        #pragma unroll
        for (int j = 0; j < 4; j++) {
            int col = n0 + tx * 4 + j;
            g_tmp[(size_t)row * DD + col] = vv[j] + bo[col] + x[(size_t)row * DD + col];
        }
    }
}

// ---------------- 7. LayerNorm ----------------
__global__ void __launch_bounds__(256) k_ln(const float* __restrict__ gamma,
                                            const float* __restrict__ beta,
                                            float* __restrict__ out) {
    const int n = blockIdx.x, tid = threadIdx.x;
    float v = g_tmp[(size_t)n * DD + tid];
    __shared__ float red[8];
    float s = v;
    #pragma unroll
    for (int o = 16; o > 0; o >>= 1) s += __shfl_xor_sync(0xffffffffu, s, o);
    if ((tid & 31) == 0) red[tid >> 5] = s;
    __syncthreads();
    float tot = 0.f;
    #pragma unroll
    for (int i = 0; i < 8; i++) tot += red[i];
    float mu = tot * (1.0f / DD);
    float d = v - mu;
    __syncthreads();
    float sq = d * d;
    #pragma unroll
    for (int o = 16; o > 0; o >>= 1) sq += __shfl_xor_sync(0xffffffffu, sq, o);
    if ((tid & 31) == 0) red[tid >> 5] = sq;
    __syncthreads();
    float tot2 = 0.f;
    #pragma unroll
    for (int i = 0; i < 8; i++) tot2 += red[i];
    float var = tot2 * (1.0f / DD);
    out[(size_t)n * DD + tid] = d * rsqrtf(var + 1e-5f) * gamma[tid] + beta[tid];
}

// ---------------- launch ----------------
extern "C" void kernel_launch(void* const* d_in, const int* in_sizes, int n_in,
                              void* d_out, int out_size) {
    const float* x       = (const float*)d_in[0];
    const float* pos     = (const float*)d_in[1];
    const int* ei        = (const int*)d_in[2];
    const int* et        = (const int*)d_in[3];
    const float* Wq = (const float*)d_in[4];
    const float* bq = (const float*)d_in[5];
    const float* Wk = (const float*)d_in[6];
    const float* bk = (const float*)d_in[7];
    const float* Wv = (const float*)d_in[8];
    const float* bv = (const float*)d_in[9];
    const float* Wo = (const float*)d_in[10];
    const float* bo = (const float*)d_in[11];
    const float* emb   = (const float*)d_in[12];
    const float* gamma = (const float*)d_in[13];
    const float* beta  = (const float*)d_in[14];
    float* out = (float*)d_out;

    cudaFuncSetAttribute(k_flash3, cudaFuncAttributeMaxDynamicSharedMemorySize, SM3);

    k_qkv<<<dim3(DD / 64, NN / 64, 3), 256>>>(x, pos, Wq, bq, Wk, bk, Wv, bv);
    k_split_vt<<<HH * NN / 256, 256>>>();
    k_zero<<<(NN + 255) / 256, 256>>>();
    k_count<<<EE / 256, 256>>>(ei);
    k_scan<<<1, 1024>>>();
    k_scatter<<<EE / 256, 256>>>(ei, et);
    k_sort<<<NN / 128, 128>>>();
    k_flash3<<<dim3(NN / 128, HH), 256, SM3>>>();
    k_corr<<<(NN * HH) / 256, 256>>>(emb);
    k_oproj<<<dim3(DD / 64, NN / 64), 256>>>(Wo, bo, x);
    k_ln<<<NN, 256>>>(gamma, beta, out);
}